// round 15
// baseline (speedup 1.0000x reference)
#include <cuda_runtime.h>
#include <cuda_bf16.h>
#include <cuda_fp16.h>

#define N_    32
#define CIN   32
#define V_    500
#define T_    96
#define L_    94      // T - K + 1
#define COUT  64
#define VP    512     // padded v/w dim
#define LP    96      // padded l dim in g_xt

// Scratch (zero-initialized at module load; padding regions never written)
__device__ float          g_xt  [N_ * CIN * LP * VP];     // fp32 (fallback only)
__device__ __half         g_xth [N_ * CIN * LP * VP];     // fp16 xt (kernelC A + kernelD hop0)
__device__ float          g_x12 [2 * N_ * CIN * L_ * VP]; // fp32 (fallback only)
__device__ __half         g_x12h[2 * N_ * CIN * L_ * VP]; // fp16 x1/x2 (for kernelD)
__device__ float          g_Apad [VP * VP];               // fallback
__device__ float          g_A2pad[VP * VP];               // fallback
__device__ __half         g_ATh [VP * VP];                // A^T   fp16
__device__ __half         g_A2Th[VP * VP];                // (A@A)^T fp16
// xp, pre-swizzled: [n][vc=4][t=96] blocks of 4096 floats; elem (vr,ci) at SW128(vr*128+ci*4)
__device__ float          g_xpsw[N_ * 4 * T_ * 4096];
// stacked conv weights, INTERLEAVED: row = c*4 + j (j=0,1,2 conv; j=3 zero)
__device__ float          g_Wcat[128 * 96];

#define HAS_TCGEN05 (defined(__CUDA_ARCH_FEAT_SM103_ALL) || defined(__CUDA_ARCH_FEAT_SM100_ALL) || defined(__CUDA_ARCH_FEAT_SM101_ALL))

#define SW128(o) ((o) ^ (((o) >> 3) & 0x70))

static __device__ __forceinline__ unsigned smem_u32(const void* p) {
    unsigned a;
    asm("{ .reg .u64 t; cvta.to.shared.u64 t, %1; cvt.u32.u64 %0, t; }"
        : "=r"(a) : "l"(p));
    return a;
}

static __device__ __forceinline__ float tf32r(float x) {
    float r;
    asm("cvt.rna.tf32.f32 %0, %1;" : "=f"(r) : "f"(x));
    return r;
}

#if HAS_TCGEN05
static __device__ __forceinline__ unsigned elect_one() {
    unsigned p;
    asm volatile("{\n\t.reg .pred p;\n\telect.sync _|p, 0xFFFFFFFF;\n\t"
                 "selp.b32 %0, 1, 0, p;\n\t}" : "=r"(p));
    return p;
}

static __device__ __forceinline__ void mbar_wait_parity(unsigned mbar, unsigned phase) {
    asm volatile(
        "{\n\t.reg .pred P1;\n\t"
        "WL_%=:\n\t"
        "mbarrier.try_wait.parity.acquire.cta.shared::cta.b64 P1, [%0], %1, 0x989680;\n\t"
        "@P1 bra.uni WD_%=;\n\t"
        "bra.uni WL_%=;\n\t"
        "WD_%=:\n\t}"
        :: "r"(mbar), "r"(phase) : "memory");
}

static __device__ __forceinline__ void mma_f16_ss(unsigned d_tmem, unsigned long long a_desc,
                                                  unsigned long long b_desc, unsigned idesc,
                                                  unsigned en) {
    asm volatile(
        "{\n\t.reg .pred p;\n\t"
        "setp.ne.u32 p, %4, 0;\n\t"
        "tcgen05.mma.cta_group::1.kind::f16 [%0], %1, %2, %3, {%5, %5, %5, %5}, p;\n\t}"
        :: "r"(d_tmem), "l"(a_desc), "l"(b_desc), "r"(idesc), "r"(en), "r"(0u)
        : "memory");
}

static __device__ __forceinline__ void mma_tf32_ss(unsigned d_tmem, unsigned long long a_desc,
                                                   unsigned long long b_desc, unsigned idesc,
                                                   unsigned en) {
    asm volatile(
        "{\n\t.reg .pred p;\n\t"
        "setp.ne.u32 p, %4, 0;\n\t"
        "tcgen05.mma.cta_group::1.kind::tf32 [%0], %1, %2, %3, {%5, %5, %5, %5}, p;\n\t}"
        :: "r"(d_tmem), "l"(a_desc), "l"(b_desc), "r"(idesc), "r"(en), "r"(0u)
        : "memory");
}

static __device__ __forceinline__ void ldtm_x32(unsigned* r, unsigned addr) {
    asm volatile(
        "tcgen05.ld.sync.aligned.32x32b.x32.b32 "
        "{%0, %1, %2, %3, %4, %5, %6, %7, "
        " %8, %9, %10, %11, %12, %13, %14, %15, "
        " %16, %17, %18, %19, %20, %21, %22, %23, "
        " %24, %25, %26, %27, %28, %29, %30, %31}, [%32];"
        : "=r"(r[0]),  "=r"(r[1]),  "=r"(r[2]),  "=r"(r[3]),
          "=r"(r[4]),  "=r"(r[5]),  "=r"(r[6]),  "=r"(r[7]),
          "=r"(r[8]),  "=r"(r[9]),  "=r"(r[10]), "=r"(r[11]),
          "=r"(r[12]), "=r"(r[13]), "=r"(r[14]), "=r"(r[15]),
          "=r"(r[16]), "=r"(r[17]), "=r"(r[18]), "=r"(r[19]),
          "=r"(r[20]), "=r"(r[21]), "=r"(r[22]), "=r"(r[23]),
          "=r"(r[24]), "=r"(r[25]), "=r"(r[26]), "=r"(r[27]),
          "=r"(r[28]), "=r"(r[29]), "=r"(r[30]), "=r"(r[31])
        : "r"(addr));
}

#define DESC_BASE ((2ULL << 61) | (1ULL << 46) | (64ULL << 32) | (1ULL << 16))
#endif  // HAS_TCGEN05

// ---------------------------------------------------------------------------
// Kernel A: A@A; emit fp32 padded (fallback) + fp16 transposed
// ---------------------------------------------------------------------------
__global__ __launch_bounds__(256) void kernelA(const float* __restrict__ A) {
    __shared__ float As[16][16];
    __shared__ float Bs[16][16];
    int tx = threadIdx.x, ty = threadIdx.y;
    int w = blockIdx.x * 16 + tx;
    int v = blockIdx.y * 16 + ty;
    float aval = (v < V_ && w < V_) ? A[v * V_ + w] : 0.f;
    float acc = 0.f;
    for (int u0 = 0; u0 < V_; u0 += 16) {
        int u1 = u0 + tx, u2 = u0 + ty;
        As[ty][tx] = (v < V_ && u1 < V_) ? A[v * V_ + u1] : 0.f;
        Bs[ty][tx] = (u2 < V_ && w < V_) ? A[u2 * V_ + w] : 0.f;
        __syncthreads();
#pragma unroll
        for (int u = 0; u < 16; u++) acc += As[ty][u] * Bs[u][tx];
        __syncthreads();
    }
    float a2val = (v < V_ && w < V_) ? acc : 0.f;
    g_Apad [v * VP + w] = aval;
    g_A2pad[v * VP + w] = a2val;
    g_ATh [w * VP + v] = __float2half_rn(aval);
    g_A2Th[w * VP + v] = __float2half_rn(a2val);
}

// ---------------------------------------------------------------------------
// Kernel W: interleaved Wcat: row = c*4 + j; col k' = kk*32 + ci (tf32)
// ---------------------------------------------------------------------------
__global__ __launch_bounds__(256) void kernelW(
    const float* __restrict__ w1, const float* __restrict__ w2,
    const float* __restrict__ w3)
{
    int idx = blockIdx.x * 256 + threadIdx.x;
    if (idx < 128 * 96) {
        int row = idx / 96, kp = idx % 96;
        int c = row >> 2, j = row & 3;
        int kk = kp >> 5, ci = kp & 31;
        float val = 0.f;
        if (j == 0)      val = w1[c * 96 + ci * 3 + kk];
        else if (j == 1) val = w2[c * 96 + ci * 3 + kk];
        else if (j == 2) val = w3[c * 96 + ci * 3 + kk];
        g_Wcat[idx] = tf32r(val);
    }
}

// ---------------------------------------------------------------------------
// Kernel X: x[n][ci][v][t] -> g_xpsw swizzled atom-col blocks (tf32-rounded)
// ---------------------------------------------------------------------------
#define X_SMEM (4 * 96 * 33 * 4)
__global__ __launch_bounds__(256) void kernelX(const float* __restrict__ x) {
    extern __shared__ float xs[];          // [vt][33]
    int v0 = blockIdx.x * 4, n = blockIdx.y;
    int tid = threadIdx.x;
    for (int i = tid; i < CIN * 4 * T_; i += 256) {
        int t  = i % T_;
        int r  = i / T_;
        int vi = r & 3;
        int ci = r >> 2;
        xs[(vi * T_ + t) * 33 + ci] = x[((n * CIN + ci) * V_ + v0 + vi) * T_ + t];
    }
    __syncthreads();
    for (int i = tid; i < 3072; i += 256) {
        int ci4 = i & 7;
        int r   = i >> 3;            // vi*96 + t
        int t   = r % 96;
        int vi  = r / 96;
        const float* s = &xs[r * 33 + ci4 * 4];
        float4 o;
        o.x = tf32r(s[0]); o.y = tf32r(s[1]); o.z = tf32r(s[2]); o.w = tf32r(s[3]);
        int v = v0 + vi, vc = v >> 7, vr = v & 127;
        *(float4*)&g_xpsw[((size_t)(n * 4 + vc) * T_ + t) * 4096
                          + (SW128(vr * 128 + ci4 * 16) >> 2)] = o;
    }
}

// ---------------------------------------------------------------------------
// Kernel B (tcgen05 tf32): pipelined, 2 CTAs/SM (ring of 3 t-cols, ~97KB smem).
// Per CTA (vc, n, lhalf).  1-l batches, TMEM 256 cols (2 buf x 128).
// Loop: WAIT(i-1) -> STAGE(i) -> sync -> ISSUE(i) -> EPI(i-1)  (no tail sync).
// Epilogue over all 8 warps; emits fp16 g_xth ONLY.
// grid (4, 64), 256 threads.
// ---------------------------------------------------------------------------
#define BRING 3
#define BM_SMEM (1024 + 49152 + BRING * 16384 + 64)

__global__ __launch_bounds__(256) void kernelB_mma(
    const float* __restrict__ b1, const float* __restrict__ b2,
    const float* __restrict__ b3)
{
    int tid = threadIdx.x, wid = tid >> 5;
    int vc = blockIdx.x;
    int n = blockIdx.y >> 1;
    int lhalf = blockIdx.y & 1;
    int lbase = lhalf * 48;
    int lend  = (lbase + 48 < 94) ? (lbase + 48) : 94;
    int v0 = vc * 128;
    __shared__ float sb[96];
    if (tid < 96) sb[tid] = (tid < 32) ? b1[tid] : (tid < 64) ? b2[tid - 32] : b3[tid - 64];

#if HAS_TCGEN05
    extern __shared__ char smem[];
    unsigned s0 = smem_u32(smem);
    unsigned sW = (s0 + 1023) & ~1023u;
    unsigned sR = sW + 49152;
    unsigned sCtl = sR + BRING * 16384;   // [0:4) tmem, [8:16) mbar0, [16:24) mbar1
    char* pW = smem + (sW - s0);
    char* pR = smem + (sR - s0);

    if (wid == 0) {
        asm volatile("tcgen05.alloc.cta_group::1.sync.aligned.shared::cta.b32 [%0], %1;"
                     :: "r"(sCtl), "r"(256) : "memory");
        asm volatile("tcgen05.relinquish_alloc_permit.cta_group::1.sync.aligned;");
    }
    if (tid == 0) {
        asm volatile("mbarrier.init.shared.b64 [%0], %1;" :: "r"(sCtl + 8), "r"(1) : "memory");
        asm volatile("mbarrier.init.shared.b64 [%0], %1;" :: "r"(sCtl + 16), "r"(1) : "memory");
    }

    for (int i = tid; i < 128 * 24; i += 256) {
        int row = i / 24, kq = (i % 24) * 4;
        unsigned off = (kq >> 5) * 16384 + (row >> 3) * 1024 + SW128((row & 7) * 128 + (kq & 31) * 4);
        *(float4*)(pW + off) = *(const float4*)&g_Wcat[row * 96 + kq];
    }
    __syncthreads();
    unsigned tmem;
    asm volatile("ld.shared.b32 %0, [%1];" : "=r"(tmem) : "r"(sCtl));

    const unsigned idesc = (1u << 4) | (2u << 7) | (2u << 10) | (16u << 17) | (8u << 24);
    unsigned long long wdesc = DESC_BASE | ((unsigned long long)(sW >> 4) & 0x3FFF);
    unsigned long long rdesc = DESC_BASE | ((unsigned long long)(sR >> 4) & 0x3FFF);

    const float* xbase = g_xpsw + (size_t)(n * 4 + vc) * T_ * 4096;
    int tcap = (lend + 2 < 96) ? (lend + 2) : 96;
    int nb = lend - lbase;              // 1-l batches
    int staged = lbase;

    #define B_STAGE(i) do {                                                    \
        int tgt = lbase + (i) + 3; if (tgt > tcap) tgt = tcap;                 \
        for (; staged < tgt; staged++) {                                       \
            const float4* src = (const float4*)(xbase + (size_t)staged * 4096);\
            float4* dst = (float4*)(pR + (staged % 3) * 16384);                \
            for (int j = tid; j < 1024; j += 256) dst[j] = src[j];             \
        }                                                                      \
        asm volatile("fence.proxy.async.shared::cta;" ::: "memory");           \
    } while (0)

    #define B_ISSUE(i) do {                                                    \
        if (wid == 0 && elect_one()) {                                         \
            asm volatile("tcgen05.fence::after_thread_sync;" ::: "memory");    \
            int l = lbase + (i);                                               \
            _Pragma("unroll")                                                  \
            for (int s = 0; s < 12; s++) {                                     \
                unsigned long long ad = rdesc +                                \
                    (unsigned long long)(((l + (s >> 2)) % 3) * 1024 + (s & 3) * 2); \
                unsigned long long bd = wdesc +                                \
                    (unsigned long long)((s >> 2) * 1024 + (s & 3) * 2);       \
                mma_tf32_ss(tmem + ((i) & 1) * 128, ad, bd, idesc, s > 0 ? 1u : 0u); \
            }                                                                  \
            asm volatile("tcgen05.commit.cta_group::1.mbarrier::arrive::one.shared::cluster.b64 [%0];" \
                         :: "r"(sCtl + 8 + ((i) & 1) * 8) : "memory");         \
        }                                                                      \
    } while (0)

    #define B_WAIT(jb) do {                                                    \
        mbar_wait_parity(sCtl + 8 + ((jb) & 1) * 8, (unsigned)(((jb) >> 1) & 1)); \
        asm volatile("tcgen05.fence::after_thread_sync;" ::: "memory");        \
    } while (0)

    #define B_EPI(jb) do {                                                     \
        {                                                                      \
            int half = tid >> 7;                                               \
            int v = v0 + (tid & 127);                                          \
            int l = lbase + (jb);                                              \
            unsigned tb = tmem + ((jb) & 1) * 128;                             \
            _Pragma("unroll")                                                  \
            for (int gi = 0; gi < 2; gi++) {                                   \
                int g = half * 2 + gi;                                         \
                unsigned q[32];                                                \
                ldtm_x32(q, tb + g * 32);                                      \
                asm volatile("tcgen05.wait::ld.sync.aligned;" ::: "memory");   \
                if (v < V_) {                                                  \
                    _Pragma("unroll")                                          \
                    for (int cc = 0; cc < 8; cc++) {                           \
                        int c = g * 8 + cc;                                    \
                        float t1 = __uint_as_float(q[cc * 4 + 0]) + sb[c];      \
                        float t2 = __uint_as_float(q[cc * 4 + 1]) + sb[32 + c]; \
                        float t3 = __uint_as_float(q[cc * 4 + 2]) + sb[64 + c]; \
                        float r = t1 + 1.f / (1.f + __expf(-t2)) + t3;         \
                        r = fmaxf(r, 0.f);                                     \
                        int idx = ((n * CIN + c) * LP + l) * VP + v;           \
                        g_xth[idx] = __float2half_rn(r);                       \
                    }                                                          \
                }                                                              \
            }                                                                  \
            asm volatile("tcgen05.fence::before_thread_sync;" ::: "memory");   \
        }                                                                      \
    } while (0)

    B_STAGE(0);
    __syncthreads();
    B_ISSUE(0);
    for (int i = 1; i < nb; i++) {
        B_WAIT(i - 1);         // MMA(i-1) done -> ring slot of col i-1 reusable
        B_STAGE(i);
        __syncthreads();       // also orders epi(i-2) before ISSUE(i) TMEM reuse
        B_ISSUE(i);            // overlaps epilogue body below
        B_EPI(i - 1);
    }
    B_WAIT(nb - 1);
    B_EPI(nb - 1);
    __syncthreads();

    if (wid == 0)
        asm volatile("tcgen05.dealloc.cta_group::1.sync.aligned.b32 %0, %1;"
                     :: "r"(tmem), "r"(256));
    if (tid == 0) {
        asm volatile("mbarrier.inval.shared.b64 [%0];" :: "r"(sCtl + 8) : "memory");
        asm volatile("mbarrier.inval.shared.b64 [%0];" :: "r"(sCtl + 16) : "memory");
    }
    #undef B_STAGE
    #undef B_ISSUE
    #undef B_WAIT
    #undef B_EPI
#else
    __syncthreads();
    for (int i = tid; i < (lend - lbase) * 32 * 128; i += 256) {
        int l = lbase + i / (32 * 128);
        int r = i % (32 * 128);
        int c = r >> 7, vi = r & 127;
        int v = v0 + vi;
        if (v < V_) {
            float a1 = 0.f, a2 = 0.f, a3 = 0.f;
            for (int k = 0; k < 96; k++) {
                int kk = k >> 5, ci = k & 31;
                float xv = g_xpsw[((size_t)(n * 4 + vc) * T_ + l + kk) * 4096
                                  + (SW128(vi * 128 + ci * 4) >> 2)];
                a1 = fmaf(g_Wcat[(c * 4 + 0) * 96 + k], xv, a1);
                a2 = fmaf(g_Wcat[(c * 4 + 1) * 96 + k], xv, a2);
                a3 = fmaf(g_Wcat[(c * 4 + 2) * 96 + k], xv, a3);
            }
            float r2 = (a1 + sb[c]) + 1.f / (1.f + __expf(-(a2 + sb[32 + c]))) + (a3 + sb[64 + c]);
            r2 = fmaxf(r2, 0.f);
            int idx = ((n * CIN + c) * LP + l) * VP + v;
            g_xt [idx] = r2;
            g_xth[idx] = __float2half_rn(r2);
        }
    }
#endif
}

// ---------------------------------------------------------------------------
// Kernel C: diffusion GEMM — fp16 tcgen05 (kind::f16, F16 inputs), A-tile
// reused across 2 w-tiles, register prefetch, 2 CTAs/SM.
// grid (4, 24, 32): x = mat*2 + whalf, y = m-tile, z = n.  256 threads.
// Epilogue emits fp16 g_x12h.
// ---------------------------------------------------------------------------
#define C_SMEM_BYTES (80 * 1024)

__global__ __launch_bounds__(256) void kernelC() {
    extern __shared__ char smem[];
    __shared__ int rowbase[128];
    __shared__ int obase[128];

    int tid = threadIdx.x, wid = tid >> 5, lid = tid & 31;
    int mat = blockIdx.x >> 1;
    int wh  = blockIdx.x & 1;
    int m0  = blockIdx.y * 128;
    int n   = blockIdx.z;

    if (tid < 128) {
        int m = m0 + tid;
        bool valid = m < CIN * L_;
        int mm = valid ? m : 0;
        int c = mm / L_, l = mm % L_;
        rowbase[tid] = ((n * CIN + c) * LP + l) * VP;
        obase[tid]   = valid ? ((((mat * N_ + n) * CIN + c) * L_ + l) * VP) : -1;
    }

#if HAS_TCGEN05
    unsigned s0 = smem_u32(smem);
    unsigned sA = (s0 + 1023) & ~1023u;
    unsigned sB0 = sA + 16384;
    unsigned sB1 = sB0 + 16384;
    unsigned sCtl = sB1 + 16384;
    char* pA  = smem + (sA - s0);
    char* pB0 = smem + (sB0 - s0);
    char* pB1 = smem + (sB1 - s0);
    const __half* __restrict__ Bm = mat ? g_A2Th : g_ATh;

    if (wid == 0) {
        asm volatile("tcgen05.alloc.cta_group::1.sync.aligned.shared::cta.b32 [%0], %1;"
                     :: "r"(sCtl), "r"(256) : "memory");
        asm volatile("tcgen05.relinquish_alloc_permit.cta_group::1.sync.aligned;");
    }
    if (tid == 0)
        asm volatile("mbarrier.init.shared.b64 [%0], %1;" :: "r"(sCtl + 8), "r"(1) : "memory");
    __syncthreads();
    unsigned tmem;
    asm volatile("ld.shared.b32 %0, [%1];" : "=r"(tmem) : "r"(sCtl));

    // kind::f16 with F16 inputs: dtype=F32 (1<<4), atype=btype=F16 (0), N=128, M=128
    const unsigned idesc = (1u << 4) | (16u << 17) | (8u << 24);
    unsigned long long adesc  = DESC_BASE | ((unsigned long long)(sA  >> 4) & 0x3FFF);
    unsigned long long b0desc = DESC_BASE | ((unsigned long long)(sB0 >> 4) & 0x3FFF);
    unsigned long long b1desc = DESC_BASE | ((unsigned long long)(sB1 >> 4) & 0x3FFF);

    const __half* pa4[4];
    const __half* pb0[4];
    const __half* pb1[4];
    unsigned swo[4];
#pragma unroll
    for (int it = 0; it < 4; it++) {
        int idx = tid + it * 256;
        int row = idx >> 3, c16 = idx & 7;
        swo[it] = SW128((unsigned)(row * 128 + c16 * 16));
        pa4[it] = &g_xth[rowbase[row] + c16 * 8];
        pb0[it] = &Bm[(wh * 256 + row) * VP + c16 * 8];
        pb1[it] = &Bm[(wh * 256 + 128 + row) * VP + c16 * 8];
    }
    float4 va[4], vb0[4], vb1[4];
#pragma unroll
    for (int it = 0; it < 4; it++) {
        va[it]  = *(const float4*)pa4[it];
        vb0[it] = *(const float4*)pb0[it];
        vb1[it] = *(const float4*)pb1[it];
    }

    for (int kc = 0; kc < 8; kc++) {
#pragma unroll
        for (int it = 0; it < 4; it++) {
            *(float4*)(pA  + swo[it]) = va[it];
            *(float4*)(pB0 + swo[it]) = vb0[it];
            *(float4*)(pB1 + swo[it]) = vb1[it];
        }
        asm volatile("fence.proxy.async.shared::cta;" ::: "memory");
        __syncthreads();
        if (wid == 0 && elect_one()) {
#pragma unroll
            for (int j = 0; j < 4; j++)
                mma_f16_ss(tmem, adesc + j * 2, b0desc + j * 2, idesc,
                           (kc > 0 || j > 0) ? 1u : 0u);
#pragma unroll
            for (int j = 0; j < 4; j++)
                mma_f16_ss(tmem + 128, adesc + j * 2, b1desc + j * 2, idesc,
                           (kc > 0 || j > 0) ? 1u : 0u);
            asm volatile(
                "tcgen05.commit.cta_group::1.mbarrier::arrive::one.shared::cluster.b64 [%0];"
                :: "r"(sCtl + 8) : "memory");
        }
        if (kc < 7) {
            int k1 = (kc + 1) * 64;
#pragma unroll
            for (int it = 0; it < 4; it++) {
                va[it]  = *(const float4*)(pa4[it] + k1);
                vb0[it] = *(const float4*)(pb0[it] + k1);
                vb1[it] = *(const float4*)(pb1[it] + k1);
            }
        }
        mbar_wait_parity(sCtl + 8, (unsigned)(kc & 1));
    }

    asm volatile("tcgen05.fence::after_thread_sync;" ::: "memory");

    if (wid < 4) {
        int row = wid * 32 + lid;
        int ob = obase[row];
#pragma unroll
        for (int acc = 0; acc < 2; acc++) {
#pragma unroll
            for (int g = 0; g < 4; g++) {
                unsigned r[32];
                ldtm_x32(r, tmem + acc * 128 + g * 32);
                asm volatile("tcgen05.wait::ld.sync.aligned;" ::: "memory");
                if (ob >= 0) {
#pragma unroll
                    for (int q = 0; q < 4; q++) {       // 8 cols per 16B store
                        __half2 h[4];
#pragma unroll
                        for (int m = 0; m < 4; m++)
                            h[m] = __floats2half2_rn(
                                __uint_as_float(r[q * 8 + m * 2]),
                                __uint_as_float(r[q * 8 + m * 2 + 1]));
                        *(uint4*)&g_x12h[ob + wh * 256 + acc * 128 + g * 32 + q * 8]
                            = *(uint4*)h;
                    }
                }
            }
        }
    }
    __syncthreads();
    if (tid == 0)
        asm volatile("mbarrier.inval.shared.b64 [%0];" :: "r"(sCtl + 8) : "memory");
    if (wid == 0)
        asm volatile("tcgen05.dealloc.cta_group::1.sync.aligned.b32 %0, %1;"
                     :: "r"(tmem), "r"(256));
#else
    (void)wid; (void)lid;
    float* As = (float*)smem;
    float* Bs = As + 16 * 132;
    const float* __restrict__ Bmf = mat ? g_A2pad : g_Apad;
    __syncthreads();
    int ty = tid >> 4, tx = tid & 15;
    for (int wsel = 0; wsel < 2; wsel++) {
        int w0 = wh * 256 + wsel * 128;
        float acc[8][8] = {};
        for (int k0 = 0; k0 < VP; k0 += 16) {
            __syncthreads();
#pragma unroll
            for (int it = 0; it < 2; it++) {
                int i = tid + it * 256;
                int arow = i >> 2, aq = i & 3;
                float4 va2 = *(const float4*)&g_xt[rowbase[arow] + k0 + aq * 4];
                As[(aq * 4 + 0) * 132 + arow] = va2.x;
                As[(aq * 4 + 1) * 132 + arow] = va2.y;
                As[(aq * 4 + 2) * 132 + arow] = va2.z;
                As[(aq * 4 + 3) * 132 + arow] = va2.w;
                int bk = i >> 5, bw = (i & 31) * 4;
                float4 vb2 = *(const float4*)&Bmf[(k0 + bk) * VP + w0 + bw];
                *(float4*)&Bs[bk * 132 + bw] = vb2;
            }
            __syncthreads();
#pragma unroll
            for (int kk = 0; kk < 16; kk++) {
                float4 a0 = *(const float4*)&As[kk * 132 + ty * 8];
                float4 a1 = *(const float4*)&As[kk * 132 + ty * 8 + 4];
                float4 b0 = *(const float4*)&Bs[kk * 132 + tx * 8];
                float4 b1v = *(const float4*)&Bs[kk * 132 + tx * 8 + 4];
                float ar[8] = {a0.x, a0.y, a0.z, a0.w, a1.x, a1.y, a1.z, a1.w};
                float br[8] = {b0.x, b0.y, b0.z, b0.w, b1v.x, b1v.y, b1v.z, b1v.w};
#pragma unroll
                for (int i = 0; i < 8; i++)
#pragma unroll
                    for (int j = 0; j < 8; j++)
                        acc[i][j] = fmaf(ar[i], br[j], acc[i][j]);
            }
        }
#pragma unroll
        for (int i = 0; i < 8; i++) {
            int ob = obase[ty * 8 + i];
            if (ob >= 0) {
                *(float4*)&g_x12[ob + w0 + tx * 8]     = make_float4(acc[i][0], acc[i][1], acc[i][2], acc[i][3]);
                *(float4*)&g_x12[ob + w0 + tx * 8 + 4] = make_float4(acc[i][4], acc[i][5], acc[i][6], acc[i][7]);
                __half2 h[4];
#pragma unroll
                for (int m2 = 0; m2 < 4; m2++)
                    h[m2] = __floats2half2_rn(acc[i][m2 * 2], acc[i][m2 * 2 + 1]);
                *(uint4*)&g_x12h[ob + w0 + tx * 8] = *(uint4*)h;
            }
        }
        __syncthreads();
    }
#endif
}

// ---------------------------------------------------------------------------
// Kernel D (tcgen05 tf32): projection + PReLU.  SINGLE A-buffer (~73KB smem
// -> 3 CTAs/SM), TMEM double buffer.  A staged from fp16 (g_xth / g_x12h).
// Loop: WAIT(t-1) -> stage(t) -> sync -> issue(t) -> epi(t-1)  (no tail sync).
// grid (4, 64).
// ---------------------------------------------------------------------------
#define D_SMEM (1024 + 24576 + 49152 + 64)

#if HAS_TCGEN05
static __device__ __forceinline__ void d_stage(
    int tid, int tau, int lbase, int n, int w0, char* pA)
{
    int wq = tau & 7, lb = tau >> 3;
    for (int i = tid; i < 1536; i += 256) {
        int k = i >> 4;               // 0..95
        int lslot = (i >> 1) & 7;
        int h16 = i & 1;
        int hop = k >> 5, c = k & 31;
        int l = lbase + lb * 8 + lslot;
        int lcl = l > 93 ? 93 : l;
        const __half* src;
        if (hop == 0)
            src = g_xth + ((size_t)(n * CIN + c) * LP + lcl) * VP + w0 + wq * 16 + h16 * 8;
        else
            src = g_x12h + ((size_t)(((hop - 1) * N_ + n) * CIN + c) * L_ + lcl) * VP
                  + w0 + wq * 16 + h16 * 8;
        uint4 raw = *(const uint4*)src;           // 8 halves
        const __half2* hp = (const __half2*)&raw;
        unsigned basew = hop * 16384 + SW128(lslot * 128 + (k & 31) * 4);
#pragma unroll
        for (int m = 0; m < 4; m++) {
            float2 f = __half22float2(hp[m]);
            int wsub0 = h16 * 8 + m * 2;
            *(float*)(pA + basew + wsub0 * 1024)       = tf32r(f.x);
            *(float*)(pA + basew + (wsub0 + 1) * 1024) = tf32r(f.y);
        }
    }
}

static __device__ __forceinline__ void d_epilogue(
    int tid, int tau, int lbase, int n, int w0, unsigned tmem,
    const float* sbo, float spa, float* out)
{
    int half = tid >> 7;
    int r = tid & 127;
    int wsub = r >> 3, lslot = r & 7;
    int wq = tau & 7, lb = tau >> 3;
    int l = lbase + lb * 8 + lslot;
    int w = w0 + wq * 16 + wsub;
    unsigned q[32];
    unsigned base = tmem + (tau & 1) * 64 + half * 32;
    ldtm_x32(q, base);
    asm volatile("tcgen05.wait::ld.sync.aligned;" ::: "memory");
    if (w < V_ && l < L_) {
        float* ob = out + (((size_t)n * COUT + half * 32) * V_ + w) * L_ + l;
#pragma unroll
        for (int o = 0; o < 32; o++) {
            float val = __uint_as_float(q[o]) + sbo[half * 32 + o];
            val = val > 0.f ? val : spa * val;
            ob[(size_t)o * V_ * L_] = val;
        }
    }
    asm volatile("tcgen05.fence::before_thread_sync;" ::: "memory");
}
#endif

__global__ __launch_bounds__(256) void kernelD_mma(
    const float* __restrict__ wout,
    const float* __restrict__ bout,
    const float* __restrict__ pa,
    float* __restrict__ out)
{
    int tid = threadIdx.x, wid = tid >> 5;
    int wc = blockIdx.x;
    int n = blockIdx.y >> 1;
    int lhalf = blockIdx.y & 1;
    int lbase = lhalf * 48;
    int w0 = wc * 128;
    __shared__ float sbo[64];
    __shared__ float spa;
    if (tid < 64) sbo[tid] = bout[tid];
    if (tid == 0) spa = pa[0];

#if HAS_TCGEN05
    extern __shared__ char smem[];
    unsigned s0 = smem_u32(smem);
    unsigned sWt = (s0 + 1023) & ~1023u;
    unsigned sA = sWt + 24576;
    unsigned sCtl = sA + 49152;
    char* pWt = smem + (sWt - s0);
    char* pA  = smem + (sA - s0);

    if (wid == 0) {
        asm volatile("tcgen05.alloc.cta_group::1.sync.aligned.shared::cta.b32 [%0], %1;"
                     :: "r"(sCtl), "r"(128) : "memory");
        asm volatile("tcgen05.relinquish_alloc_permit.cta_group::1.sync.aligned;");
    }
    if (tid == 0) {
        asm volatile("mbarrier.init.shared.b64 [%0], %1;" :: "r"(sCtl + 8), "r"(1) : "memory");
        asm volatile("mbarrier.init.shared.b64 [%0], %1;" :: "r"(sCtl + 16), "r"(1) : "memory");
    }

    for (int i = tid; i < 64 * 24; i += 256) {
        int row = i / 24, kq = (i % 24) * 4;
        unsigned off = (kq >> 5) * 8192 + (row >> 3) * 1024 + SW128((row & 7) * 128 + (kq & 31) * 4);
        float4 v = *(const float4*)&wout[row * 96 + kq];
        v.x = tf32r(v.x); v.y = tf32r(v.y); v.z = tf32r(v.z); v.w = tf32r(v.w);
        *(float4*)(pWt + off) = v;
    }
    asm volatile("fence.proxy.async.shared::cta;" ::: "memory");
    __syncthreads();
    unsigned tmem;
    asm volatile("ld.shared.b32 %0, [%1];" : "=r"(tmem) : "r"(sCtl));

    const unsigned idesc = (1u << 4) | (2u << 7) | (2u << 10) | (8u << 17) | (8u << 24);
    unsigned long long wdesc = DESC_BASE | ((unsigned long long)(sWt >> 4) & 0x3FFF);
    unsigned long long adesc = DESC_BASE | ((unsigned long long)(sA >> 4) & 0x3FFF);

    #define D_ISSUE(t) do {                                                    \
        if (wid == 0 && elect_one()) {                                         \
            asm volatile("tcgen05.fence::after_thread_sync;" ::: "memory");    \
            _Pragma("unroll")                                                  \
            for (int s = 0; s < 12; s++) {                                     \
                mma_tf32_ss(tmem + ((t) & 1) * 64,                             \
                            adesc + (unsigned long long)((s >> 2) * 1024 + (s & 3) * 2), \
                            wdesc + (unsigned long long)((s >> 2) * 512 + (s & 3) * 2),  \
                            idesc, s > 0 ? 1u : 0u);                           \
            }                                                                  \
            asm volatile("tcgen05.commit.cta_group::1.mbarrier::arrive::one.shared::cluster.b64 [%0];" \
                         :: "r"(sCtl + 8 + ((t) & 1) * 8) : "memory");         \
        }                                                                      \
    } while (0)

    d_stage(tid, 0, lbase, n, w0, pA);
    asm volatile("fence.proxy.async.shared::cta;" ::: "memory");
    __syncthreads();
    D_ISSUE(0);

    for (int tau = 1; tau < 48; tau++) {
        int tm1 = tau - 1;
        // MMA(tau-1) must be done before overwriting the single A buffer
        mbar_wait_parity(sCtl + 8 + (tm1 & 1) * 8, (unsigned)((tm1 >> 1) & 1));
        asm volatile("tcgen05.fence::after_thread_sync;" ::: "memory");
        d_stage(tid, tau, lbase, n, w0, pA);
        asm volatile("fence.proxy.async.shared::cta;" ::: "memory");
        __syncthreads();       // also orders epi(tau-2) before ISSUE(tau) TMEM reuse
        D_ISSUE(tau);          // overlaps epilogue(tau-1) below
        d_epilogue(tid, tm1, lbase, n, w0, tmem, sbo, spa, out);
    }
    mbar_wait_parity(sCtl + 8 + (47 & 1) * 8, (unsigned)((47 >> 1) & 1));
    asm volatile("tcgen05.fence::after_thread_sync;" ::: "memory");
    d_epilogue(tid, 47, lbase, n, w0, tmem, sbo, spa, out);
    #undef D_ISSUE

    __syncthreads();
    if (wid == 0)
        asm volatile("tcgen05.dealloc.cta_group::1.sync.aligned.b32 %0, %1;"
                     :: "r"(tmem), "r"(128));
    if (tid == 0) {
        asm volatile("mbarrier.inval.shared.b64 [%0];" :: "r"(sCtl + 8) : "memory");
        asm volatile("mbarrier.inval.shared.b64 [%0];" :: "r"(sCtl + 16) : "memory");
    }
#else
    __syncthreads();
    int lend = (lbase + 48 < 94) ? (lbase + 48) : 94;
    int nl = lend - lbase;
    for (int i = tid; i < 64 * 128 * nl; i += 256) {
        int o = i / (128 * nl);
        int r = i % (128 * nl);
        int wi = r / nl, l = lbase + r % nl;
        int w = w0 + wi;
        if (w < V_) {
            float acc = bout[o];
            for (int k = 0; k < 96; k++) {
                int hop = k >> 5, c = k & 31;
                float h;
                if (hop == 0) h = g_xt[((size_t)(n * CIN + c) * LP + l) * VP + w];
                else h = g_x12[((size_t)(((hop - 1) * N_ + n) * CIN + c) * L_ + l) * VP + w];
                acc = fmaf(wout[o * 96 + k], h, acc);
            }
            acc = acc > 0.f ? acc : spa * acc;
            out[(((size_t)n * COUT + o) * V_ + w) * L_ + l] = acc;
        }
    }
#endif
}

// ---------------------------------------------------------------------------
extern "C" void kernel_launch(void* const* d_in, const int* in_sizes, int n_in,
                              void* d_out, int out_size) {
    const float* x    = (const float*)d_in[0];
    const float* A    = (const float*)d_in[1];
    const float* w1   = (const float*)d_in[2];
    const float* b1   = (const float*)d_in[3];
    const float* w2   = (const float*)d_in[4];
    const float* b2   = (const float*)d_in[5];
    const float* w3   = (const float*)d_in[6];
    const float* b3   = (const float*)d_in[7];
    const float* wout = (const float*)d_in[8];
    const float* bout = (const float*)d_in[9];
    const float* pa   = (const float*)d_in[10];
    float* out = (float*)d_out;

    cudaFuncSetAttribute(kernelC,     cudaFuncAttributeMaxDynamicSharedMemorySize, C_SMEM_BYTES);
    cudaFuncSetAttribute(kernelB_mma, cudaFuncAttributeMaxDynamicSharedMemorySize, BM_SMEM);
    cudaFuncSetAttribute(kernelD_mma, cudaFuncAttributeMaxDynamicSharedMemorySize, D_SMEM);
    cudaFuncSetAttribute(kernelX,     cudaFuncAttributeMaxDynamicSharedMemorySize, X_SMEM);

    kernelA<<<dim3(32, 32), dim3(16, 16)>>>(A);
    kernelW<<<48, 256>>>(w1, w2, w3);
    kernelX<<<dim3(125, 32), 256, X_SMEM>>>(x);
    kernelB_mma<<<dim3(4, 64), 256, BM_SMEM>>>(b1, b2, b3);
    kernelC<<<dim3(4, 24, 32), 256, C_SMEM_BYTES>>>();
    kernelD_mma<<<dim3(4, 64), 256, D_SMEM>>>(wout, bout, pa, out);
}

// round 16
// speedup vs baseline: 1.0240x; 1.0240x over previous
#include <cuda_runtime.h>
#include <cuda_bf16.h>
#include <cuda_fp16.h>

#define N_    32
#define CIN   32
#define V_    500
#define T_    96
#define L_    94      // T - K + 1
#define COUT  64
#define VP    512     // padded v/w dim
#define LP    96      // padded l dim in g_xt

// Scratch (zero-initialized at module load; padding regions never written)
__device__ float          g_xt  [N_ * CIN * LP * VP];     // fp32 (fallback only)
__device__ __half         g_xth [N_ * CIN * LP * VP];     // fp16 xt (kernelC A + kernelD hop0)
__device__ float          g_x12 [2 * N_ * CIN * L_ * VP]; // fp32 (fallback only)
__device__ __half         g_x12h[2 * N_ * CIN * L_ * VP]; // fp16 x1/x2 (for kernelD)
__device__ float          g_Apad [VP * VP];               // fallback
__device__ float          g_A2pad[VP * VP];               // fallback
__device__ __half         g_ATh [VP * VP];                // A^T   fp16
__device__ __half         g_A2Th[VP * VP];                // (A@A)^T fp16
// xp, pre-swizzled: [n][vc=4][t=96] blocks of 4096 floats; elem (vr,ci) at SW128(vr*128+ci*4)
__device__ float          g_xpsw[N_ * 4 * T_ * 4096];
// stacked conv weights, INTERLEAVED: row = c*4 + j (j=0,1,2 conv; j=3 zero)
__device__ float          g_Wcat[128 * 96];

#define HAS_TCGEN05 (defined(__CUDA_ARCH_FEAT_SM103_ALL) || defined(__CUDA_ARCH_FEAT_SM100_ALL) || defined(__CUDA_ARCH_FEAT_SM101_ALL))

#define SW128(o) ((o) ^ (((o) >> 3) & 0x70))

static __device__ __forceinline__ unsigned smem_u32(const void* p) {
    unsigned a;
    asm("{ .reg .u64 t; cvta.to.shared.u64 t, %1; cvt.u32.u64 %0, t; }"
        : "=r"(a) : "l"(p));
    return a;
}

static __device__ __forceinline__ float tf32r(float x) {
    float r;
    asm("cvt.rna.tf32.f32 %0, %1;" : "=f"(r) : "f"(x));
    return r;
}

#if HAS_TCGEN05
static __device__ __forceinline__ unsigned elect_one() {
    unsigned p;
    asm volatile("{\n\t.reg .pred p;\n\telect.sync _|p, 0xFFFFFFFF;\n\t"
                 "selp.b32 %0, 1, 0, p;\n\t}" : "=r"(p));
    return p;
}

static __device__ __forceinline__ void mbar_wait_parity(unsigned mbar, unsigned phase) {
    asm volatile(
        "{\n\t.reg .pred P1;\n\t"
        "WL_%=:\n\t"
        "mbarrier.try_wait.parity.acquire.cta.shared::cta.b64 P1, [%0], %1, 0x989680;\n\t"
        "@P1 bra.uni WD_%=;\n\t"
        "bra.uni WL_%=;\n\t"
        "WD_%=:\n\t}"
        :: "r"(mbar), "r"(phase) : "memory");
}

static __device__ __forceinline__ void mma_f16_ss(unsigned d_tmem, unsigned long long a_desc,
                                                  unsigned long long b_desc, unsigned idesc,
                                                  unsigned en) {
    asm volatile(
        "{\n\t.reg .pred p;\n\t"
        "setp.ne.u32 p, %4, 0;\n\t"
        "tcgen05.mma.cta_group::1.kind::f16 [%0], %1, %2, %3, {%5, %5, %5, %5}, p;\n\t}"
        :: "r"(d_tmem), "l"(a_desc), "l"(b_desc), "r"(idesc), "r"(en), "r"(0u)
        : "memory");
}

static __device__ __forceinline__ void mma_tf32_ss(unsigned d_tmem, unsigned long long a_desc,
                                                   unsigned long long b_desc, unsigned idesc,
                                                   unsigned en) {
    asm volatile(
        "{\n\t.reg .pred p;\n\t"
        "setp.ne.u32 p, %4, 0;\n\t"
        "tcgen05.mma.cta_group::1.kind::tf32 [%0], %1, %2, %3, {%5, %5, %5, %5}, p;\n\t}"
        :: "r"(d_tmem), "l"(a_desc), "l"(b_desc), "r"(idesc), "r"(en), "r"(0u)
        : "memory");
}

static __device__ __forceinline__ void ldtm_x32(unsigned* r, unsigned addr) {
    asm volatile(
        "tcgen05.ld.sync.aligned.32x32b.x32.b32 "
        "{%0, %1, %2, %3, %4, %5, %6, %7, "
        " %8, %9, %10, %11, %12, %13, %14, %15, "
        " %16, %17, %18, %19, %20, %21, %22, %23, "
        " %24, %25, %26, %27, %28, %29, %30, %31}, [%32];"
        : "=r"(r[0]),  "=r"(r[1]),  "=r"(r[2]),  "=r"(r[3]),
          "=r"(r[4]),  "=r"(r[5]),  "=r"(r[6]),  "=r"(r[7]),
          "=r"(r[8]),  "=r"(r[9]),  "=r"(r[10]), "=r"(r[11]),
          "=r"(r[12]), "=r"(r[13]), "=r"(r[14]), "=r"(r[15]),
          "=r"(r[16]), "=r"(r[17]), "=r"(r[18]), "=r"(r[19]),
          "=r"(r[20]), "=r"(r[21]), "=r"(r[22]), "=r"(r[23]),
          "=r"(r[24]), "=r"(r[25]), "=r"(r[26]), "=r"(r[27]),
          "=r"(r[28]), "=r"(r[29]), "=r"(r[30]), "=r"(r[31])
        : "r"(addr));
}

#define DESC_BASE ((2ULL << 61) | (1ULL << 46) | (64ULL << 32) | (1ULL << 16))
#endif  // HAS_TCGEN05

// ---------------------------------------------------------------------------
// Kernel A: A@A; emit fp32 padded (fallback) + fp16 transposed
// ---------------------------------------------------------------------------
__global__ __launch_bounds__(256) void kernelA(const float* __restrict__ A) {
    __shared__ float As[16][16];
    __shared__ float Bs[16][16];
    int tx = threadIdx.x, ty = threadIdx.y;
    int w = blockIdx.x * 16 + tx;
    int v = blockIdx.y * 16 + ty;
    float aval = (v < V_ && w < V_) ? A[v * V_ + w] : 0.f;
    float acc = 0.f;
    for (int u0 = 0; u0 < V_; u0 += 16) {
        int u1 = u0 + tx, u2 = u0 + ty;
        As[ty][tx] = (v < V_ && u1 < V_) ? A[v * V_ + u1] : 0.f;
        Bs[ty][tx] = (u2 < V_ && w < V_) ? A[u2 * V_ + w] : 0.f;
        __syncthreads();
#pragma unroll
        for (int u = 0; u < 16; u++) acc += As[ty][u] * Bs[u][tx];
        __syncthreads();
    }
    float a2val = (v < V_ && w < V_) ? acc : 0.f;
    g_Apad [v * VP + w] = aval;
    g_A2pad[v * VP + w] = a2val;
    g_ATh [w * VP + v] = __float2half_rn(aval);
    g_A2Th[w * VP + v] = __float2half_rn(a2val);
}

// ---------------------------------------------------------------------------
// Kernel W: interleaved Wcat: row = c*4 + j; col k' = kk*32 + ci (tf32)
// ---------------------------------------------------------------------------
__global__ __launch_bounds__(256) void kernelW(
    const float* __restrict__ w1, const float* __restrict__ w2,
    const float* __restrict__ w3)
{
    int idx = blockIdx.x * 256 + threadIdx.x;
    if (idx < 128 * 96) {
        int row = idx / 96, kp = idx % 96;
        int c = row >> 2, j = row & 3;
        int kk = kp >> 5, ci = kp & 31;
        float val = 0.f;
        if (j == 0)      val = w1[c * 96 + ci * 3 + kk];
        else if (j == 1) val = w2[c * 96 + ci * 3 + kk];
        else if (j == 2) val = w3[c * 96 + ci * 3 + kk];
        g_Wcat[idx] = tf32r(val);
    }
}

// ---------------------------------------------------------------------------
// Kernel X: x[n][ci][v][t] -> g_xpsw swizzled atom-col blocks (tf32-rounded)
// ---------------------------------------------------------------------------
#define X_SMEM (4 * 96 * 33 * 4)
__global__ __launch_bounds__(256) void kernelX(const float* __restrict__ x) {
    extern __shared__ float xs[];          // [vt][33]
    int v0 = blockIdx.x * 4, n = blockIdx.y;
    int tid = threadIdx.x;
    for (int i = tid; i < CIN * 4 * T_; i += 256) {
        int t  = i % T_;
        int r  = i / T_;
        int vi = r & 3;
        int ci = r >> 2;
        xs[(vi * T_ + t) * 33 + ci] = x[((n * CIN + ci) * V_ + v0 + vi) * T_ + t];
    }
    __syncthreads();
    for (int i = tid; i < 3072; i += 256) {
        int ci4 = i & 7;
        int r   = i >> 3;            // vi*96 + t
        int t   = r % 96;
        int vi  = r / 96;
        const float* s = &xs[r * 33 + ci4 * 4];
        float4 o;
        o.x = tf32r(s[0]); o.y = tf32r(s[1]); o.z = tf32r(s[2]); o.w = tf32r(s[3]);
        int v = v0 + vi, vc = v >> 7, vr = v & 127;
        *(float4*)&g_xpsw[((size_t)(n * 4 + vc) * T_ + t) * 4096
                          + (SW128(vr * 128 + ci4 * 16) >> 2)] = o;
    }
}

// ---------------------------------------------------------------------------
// Kernel B (tcgen05 tf32): pipelined, 2 CTAs/SM (ring of 3 t-cols, ~97KB smem).
// Per CTA (vc, n, lhalf).  1-l batches, TMEM 256 cols (2 buf x 128).
// Loop: WAIT(i-1) -> STAGE(i) -> sync -> ISSUE(i) -> EPI(i-1) -> sync
// (R13 schedule).  Epilogue over all 8 warps; emits fp16 g_xth only.
// grid (4, 64), 256 threads.
// ---------------------------------------------------------------------------
#define BRING 3
#define BM_SMEM (1024 + 49152 + BRING * 16384 + 64)

__global__ __launch_bounds__(256) void kernelB_mma(
    const float* __restrict__ b1, const float* __restrict__ b2,
    const float* __restrict__ b3)
{
    int tid = threadIdx.x, wid = tid >> 5;
    int vc = blockIdx.x;
    int n = blockIdx.y >> 1;
    int lhalf = blockIdx.y & 1;
    int lbase = lhalf * 48;
    int lend  = (lbase + 48 < 94) ? (lbase + 48) : 94;
    int v0 = vc * 128;
    __shared__ float sb[96];
    if (tid < 96) sb[tid] = (tid < 32) ? b1[tid] : (tid < 64) ? b2[tid - 32] : b3[tid - 64];

#if HAS_TCGEN05
    extern __shared__ char smem[];
    unsigned s0 = smem_u32(smem);
    unsigned sW = (s0 + 1023) & ~1023u;
    unsigned sR = sW + 49152;
    unsigned sCtl = sR + BRING * 16384;   // [0:4) tmem, [8:16) mbar0, [16:24) mbar1
    char* pW = smem + (sW - s0);
    char* pR = smem + (sR - s0);

    if (wid == 0) {
        asm volatile("tcgen05.alloc.cta_group::1.sync.aligned.shared::cta.b32 [%0], %1;"
                     :: "r"(sCtl), "r"(256) : "memory");
        asm volatile("tcgen05.relinquish_alloc_permit.cta_group::1.sync.aligned;");
    }
    if (tid == 0) {
        asm volatile("mbarrier.init.shared.b64 [%0], %1;" :: "r"(sCtl + 8), "r"(1) : "memory");
        asm volatile("mbarrier.init.shared.b64 [%0], %1;" :: "r"(sCtl + 16), "r"(1) : "memory");
    }

    for (int i = tid; i < 128 * 24; i += 256) {
        int row = i / 24, kq = (i % 24) * 4;
        unsigned off = (kq >> 5) * 16384 + (row >> 3) * 1024 + SW128((row & 7) * 128 + (kq & 31) * 4);
        *(float4*)(pW + off) = *(const float4*)&g_Wcat[row * 96 + kq];
    }
    __syncthreads();
    unsigned tmem;
    asm volatile("ld.shared.b32 %0, [%1];" : "=r"(tmem) : "r"(sCtl));

    const unsigned idesc = (1u << 4) | (2u << 7) | (2u << 10) | (16u << 17) | (8u << 24);
    unsigned long long wdesc = DESC_BASE | ((unsigned long long)(sW >> 4) & 0x3FFF);
    unsigned long long rdesc = DESC_BASE | ((unsigned long long)(sR >> 4) & 0x3FFF);

    const float* xbase = g_xpsw + (size_t)(n * 4 + vc) * T_ * 4096;
    int tcap = (lend + 2 < 96) ? (lend + 2) : 96;
    int nb = lend - lbase;              // 1-l batches
    int staged = lbase;

    #define B_STAGE(i) do {                                                    \
        int tgt = lbase + (i) + 3; if (tgt > tcap) tgt = tcap;                 \
        for (; staged < tgt; staged++) {                                       \
            const float4* src = (const float4*)(xbase + (size_t)staged * 4096);\
            float4* dst = (float4*)(pR + (staged % 3) * 16384);                \
            for (int j = tid; j < 1024; j += 256) dst[j] = src[j];             \
        }                                                                      \
        asm volatile("fence.proxy.async.shared::cta;" ::: "memory");           \
    } while (0)

    #define B_ISSUE(i) do {                                                    \
        if (wid == 0 && elect_one()) {                                         \
            asm volatile("tcgen05.fence::after_thread_sync;" ::: "memory");    \
            int l = lbase + (i);                                               \
            _Pragma("unroll")                                                  \
            for (int s = 0; s < 12; s++) {                                     \
                unsigned long long ad = rdesc +                                \
                    (unsigned long long)(((l + (s >> 2)) % 3) * 1024 + (s & 3) * 2); \
                unsigned long long bd = wdesc +                                \
                    (unsigned long long)((s >> 2) * 1024 + (s & 3) * 2);       \
                mma_tf32_ss(tmem + ((i) & 1) * 128, ad, bd, idesc, s > 0 ? 1u : 0u); \
            }                                                                  \
            asm volatile("tcgen05.commit.cta_group::1.mbarrier::arrive::one.shared::cluster.b64 [%0];" \
                         :: "r"(sCtl + 8 + ((i) & 1) * 8) : "memory");         \
        }                                                                      \
    } while (0)

    #define B_WAIT(jb) do {                                                    \
        mbar_wait_parity(sCtl + 8 + ((jb) & 1) * 8, (unsigned)(((jb) >> 1) & 1)); \
        asm volatile("tcgen05.fence::after_thread_sync;" ::: "memory");        \
    } while (0)

    #define B_EPI(jb) do {                                                     \
        {                                                                      \
            int half = tid >> 7;                                               \
            int v = v0 + (tid & 127);                                          \
            int l = lbase + (jb);                                              \
            unsigned tb = tmem + ((jb) & 1) * 128;                             \
            _Pragma("unroll")                                                  \
            for (int gi = 0; gi < 2; gi++) {                                   \
                int g = half * 2 + gi;                                         \
                unsigned q[32];                                                \
                ldtm_x32(q, tb + g * 32);                                      \
                asm volatile("tcgen05.wait::ld.sync.aligned;" ::: "memory");   \
                if (v < V_) {                                                  \
                    _Pragma("unroll")                                          \
                    for (int cc = 0; cc < 8; cc++) {                           \
                        int c = g * 8 + cc;                                    \
                        float t1 = __uint_as_float(q[cc * 4 + 0]) + sb[c];      \
                        float t2 = __uint_as_float(q[cc * 4 + 1]) + sb[32 + c]; \
                        float t3 = __uint_as_float(q[cc * 4 + 2]) + sb[64 + c]; \
                        float r = t1 + 1.f / (1.f + __expf(-t2)) + t3;         \
                        r = fmaxf(r, 0.f);                                     \
                        int idx = ((n * CIN + c) * LP + l) * VP + v;           \
                        g_xth[idx] = __float2half_rn(r);                       \
                    }                                                          \
                }                                                              \
            }                                                                  \
            asm volatile("tcgen05.fence::before_thread_sync;" ::: "memory");   \
        }                                                                      \
    } while (0)

    B_STAGE(0);
    __syncthreads();
    B_ISSUE(0);
    for (int i = 1; i < nb; i++) {
        B_WAIT(i - 1);         // MMA(i-1) done -> ring slot of col i-1 reusable
        B_STAGE(i);
        __syncthreads();
        B_ISSUE(i);            // overlaps epilogue body below
        B_EPI(i - 1);
        __syncthreads();       // R13 schedule: epilogue done before next iteration
    }
    B_WAIT(nb - 1);
    B_EPI(nb - 1);
    __syncthreads();

    if (wid == 0)
        asm volatile("tcgen05.dealloc.cta_group::1.sync.aligned.b32 %0, %1;"
                     :: "r"(tmem), "r"(256));
    if (tid == 0) {
        asm volatile("mbarrier.inval.shared.b64 [%0];" :: "r"(sCtl + 8) : "memory");
        asm volatile("mbarrier.inval.shared.b64 [%0];" :: "r"(sCtl + 16) : "memory");
    }
    #undef B_STAGE
    #undef B_ISSUE
    #undef B_WAIT
    #undef B_EPI
#else
    __syncthreads();
    for (int i = tid; i < (lend - lbase) * 32 * 128; i += 256) {
        int l = lbase + i / (32 * 128);
        int r = i % (32 * 128);
        int c = r >> 7, vi = r & 127;
        int v = v0 + vi;
        if (v < V_) {
            float a1 = 0.f, a2 = 0.f, a3 = 0.f;
            for (int k = 0; k < 96; k++) {
                int kk = k >> 5, ci = k & 31;
                float xv = g_xpsw[((size_t)(n * 4 + vc) * T_ + l + kk) * 4096
                                  + (SW128(vi * 128 + ci * 4) >> 2)];
                a1 = fmaf(g_Wcat[(c * 4 + 0) * 96 + k], xv, a1);
                a2 = fmaf(g_Wcat[(c * 4 + 1) * 96 + k], xv, a2);
                a3 = fmaf(g_Wcat[(c * 4 + 2) * 96 + k], xv, a3);
            }
            float r2 = (a1 + sb[c]) + 1.f / (1.f + __expf(-(a2 + sb[32 + c]))) + (a3 + sb[64 + c]);
            r2 = fmaxf(r2, 0.f);
            int idx = ((n * CIN + c) * LP + l) * VP + v;
            g_xt [idx] = r2;
            g_xth[idx] = __float2half_rn(r2);
        }
    }
#endif
}

// ---------------------------------------------------------------------------
// Kernel C: diffusion GEMM — fp16 tcgen05 (kind::f16, F16 inputs), A-tile
// reused across 2 w-tiles, register prefetch, 2 CTAs/SM.
// grid (4, 24, 32): x = mat*2 + whalf, y = m-tile, z = n.  256 threads.
// Epilogue emits fp16 g_x12h.
// ---------------------------------------------------------------------------
#define C_SMEM_BYTES (80 * 1024)

__global__ __launch_bounds__(256) void kernelC() {
    extern __shared__ char smem[];
    __shared__ int rowbase[128];
    __shared__ int obase[128];

    int tid = threadIdx.x, wid = tid >> 5, lid = tid & 31;
    int mat = blockIdx.x >> 1;
    int wh  = blockIdx.x & 1;
    int m0  = blockIdx.y * 128;
    int n   = blockIdx.z;

    if (tid < 128) {
        int m = m0 + tid;
        bool valid = m < CIN * L_;
        int mm = valid ? m : 0;
        int c = mm / L_, l = mm % L_;
        rowbase[tid] = ((n * CIN + c) * LP + l) * VP;
        obase[tid]   = valid ? ((((mat * N_ + n) * CIN + c) * L_ + l) * VP) : -1;
    }

#if HAS_TCGEN05
    unsigned s0 = smem_u32(smem);
    unsigned sA = (s0 + 1023) & ~1023u;
    unsigned sB0 = sA + 16384;
    unsigned sB1 = sB0 + 16384;
    unsigned sCtl = sB1 + 16384;
    char* pA  = smem + (sA - s0);
    char* pB0 = smem + (sB0 - s0);
    char* pB1 = smem + (sB1 - s0);
    const __half* __restrict__ Bm = mat ? g_A2Th : g_ATh;

    if (wid == 0) {
        asm volatile("tcgen05.alloc.cta_group::1.sync.aligned.shared::cta.b32 [%0], %1;"
                     :: "r"(sCtl), "r"(256) : "memory");
        asm volatile("tcgen05.relinquish_alloc_permit.cta_group::1.sync.aligned;");
    }
    if (tid == 0)
        asm volatile("mbarrier.init.shared.b64 [%0], %1;" :: "r"(sCtl + 8), "r"(1) : "memory");
    __syncthreads();
    unsigned tmem;
    asm volatile("ld.shared.b32 %0, [%1];" : "=r"(tmem) : "r"(sCtl));

    // kind::f16 with F16 inputs: dtype=F32 (1<<4), atype=btype=F16 (0), N=128, M=128
    const unsigned idesc = (1u << 4) | (16u << 17) | (8u << 24);
    unsigned long long adesc  = DESC_BASE | ((unsigned long long)(sA  >> 4) & 0x3FFF);
    unsigned long long b0desc = DESC_BASE | ((unsigned long long)(sB0 >> 4) & 0x3FFF);
    unsigned long long b1desc = DESC_BASE | ((unsigned long long)(sB1 >> 4) & 0x3FFF);

    const __half* pa4[4];
    const __half* pb0[4];
    const __half* pb1[4];
    unsigned swo[4];
#pragma unroll
    for (int it = 0; it < 4; it++) {
        int idx = tid + it * 256;
        int row = idx >> 3, c16 = idx & 7;
        swo[it] = SW128((unsigned)(row * 128 + c16 * 16));
        pa4[it] = &g_xth[rowbase[row] + c16 * 8];
        pb0[it] = &Bm[(wh * 256 + row) * VP + c16 * 8];
        pb1[it] = &Bm[(wh * 256 + 128 + row) * VP + c16 * 8];
    }
    float4 va[4], vb0[4], vb1[4];
#pragma unroll
    for (int it = 0; it < 4; it++) {
        va[it]  = *(const float4*)pa4[it];
        vb0[it] = *(const float4*)pb0[it];
        vb1[it] = *(const float4*)pb1[it];
    }

    for (int kc = 0; kc < 8; kc++) {
#pragma unroll
        for (int it = 0; it < 4; it++) {
            *(float4*)(pA  + swo[it]) = va[it];
            *(float4*)(pB0 + swo[it]) = vb0[it];
            *(float4*)(pB1 + swo[it]) = vb1[it];
        }
        asm volatile("fence.proxy.async.shared::cta;" ::: "memory");
        __syncthreads();
        if (wid == 0 && elect_one()) {
#pragma unroll
            for (int j = 0; j < 4; j++)
                mma_f16_ss(tmem, adesc + j * 2, b0desc + j * 2, idesc,
                           (kc > 0 || j > 0) ? 1u : 0u);
#pragma unroll
            for (int j = 0; j < 4; j++)
                mma_f16_ss(tmem + 128, adesc + j * 2, b1desc + j * 2, idesc,
                           (kc > 0 || j > 0) ? 1u : 0u);
            asm volatile(
                "tcgen05.commit.cta_group::1.mbarrier::arrive::one.shared::cluster.b64 [%0];"
                :: "r"(sCtl + 8) : "memory");
        }
        if (kc < 7) {
            int k1 = (kc + 1) * 64;
#pragma unroll
            for (int it = 0; it < 4; it++) {
                va[it]  = *(const float4*)(pa4[it] + k1);
                vb0[it] = *(const float4*)(pb0[it] + k1);
                vb1[it] = *(const float4*)(pb1[it] + k1);
            }
        }
        mbar_wait_parity(sCtl + 8, (unsigned)(kc & 1));
    }

    asm volatile("tcgen05.fence::after_thread_sync;" ::: "memory");

    if (wid < 4) {
        int row = wid * 32 + lid;
        int ob = obase[row];
#pragma unroll
        for (int acc = 0; acc < 2; acc++) {
#pragma unroll
            for (int g = 0; g < 4; g++) {
                unsigned r[32];
                ldtm_x32(r, tmem + acc * 128 + g * 32);
                asm volatile("tcgen05.wait::ld.sync.aligned;" ::: "memory");
                if (ob >= 0) {
#pragma unroll
                    for (int q = 0; q < 4; q++) {       // 8 cols per 16B store
                        __half2 h[4];
#pragma unroll
                        for (int m = 0; m < 4; m++)
                            h[m] = __floats2half2_rn(
                                __uint_as_float(r[q * 8 + m * 2]),
                                __uint_as_float(r[q * 8 + m * 2 + 1]));
                        *(uint4*)&g_x12h[ob + wh * 256 + acc * 128 + g * 32 + q * 8]
                            = *(uint4*)h;
                    }
                }
            }
        }
    }
    __syncthreads();
    if (tid == 0)
        asm volatile("mbarrier.inval.shared.b64 [%0];" :: "r"(sCtl + 8) : "memory");
    if (wid == 0)
        asm volatile("tcgen05.dealloc.cta_group::1.sync.aligned.b32 %0, %1;"
                     :: "r"(tmem), "r"(256));
#else
    (void)wid; (void)lid;
    float* As = (float*)smem;
    float* Bs = As + 16 * 132;
    const float* __restrict__ Bmf = mat ? g_A2pad : g_Apad;
    __syncthreads();
    int ty = tid >> 4, tx = tid & 15;
    for (int wsel = 0; wsel < 2; wsel++) {
        int w0 = wh * 256 + wsel * 128;
        float acc[8][8] = {};
        for (int k0 = 0; k0 < VP; k0 += 16) {
            __syncthreads();
#pragma unroll
            for (int it = 0; it < 2; it++) {
                int i = tid + it * 256;
                int arow = i >> 2, aq = i & 3;
                float4 va2 = *(const float4*)&g_xt[rowbase[arow] + k0 + aq * 4];
                As[(aq * 4 + 0) * 132 + arow] = va2.x;
                As[(aq * 4 + 1) * 132 + arow] = va2.y;
                As[(aq * 4 + 2) * 132 + arow] = va2.z;
                As[(aq * 4 + 3) * 132 + arow] = va2.w;
                int bk = i >> 5, bw = (i & 31) * 4;
                float4 vb2 = *(const float4*)&Bmf[(k0 + bk) * VP + w0 + bw];
                *(float4*)&Bs[bk * 132 + bw] = vb2;
            }
            __syncthreads();
#pragma unroll
            for (int kk = 0; kk < 16; kk++) {
                float4 a0 = *(const float4*)&As[kk * 132 + ty * 8];
                float4 a1 = *(const float4*)&As[kk * 132 + ty * 8 + 4];
                float4 b0 = *(const float4*)&Bs[kk * 132 + tx * 8];
                float4 b1v = *(const float4*)&Bs[kk * 132 + tx * 8 + 4];
                float ar[8] = {a0.x, a0.y, a0.z, a0.w, a1.x, a1.y, a1.z, a1.w};
                float br[8] = {b0.x, b0.y, b0.z, b0.w, b1v.x, b1v.y, b1v.z, b1v.w};
#pragma unroll
                for (int i = 0; i < 8; i++)
#pragma unroll
                    for (int j = 0; j < 8; j++)
                        acc[i][j] = fmaf(ar[i], br[j], acc[i][j]);
            }
        }
#pragma unroll
        for (int i = 0; i < 8; i++) {
            int ob = obase[ty * 8 + i];
            if (ob >= 0) {
                *(float4*)&g_x12[ob + w0 + tx * 8]     = make_float4(acc[i][0], acc[i][1], acc[i][2], acc[i][3]);
                *(float4*)&g_x12[ob + w0 + tx * 8 + 4] = make_float4(acc[i][4], acc[i][5], acc[i][6], acc[i][7]);
                __half2 h[4];
#pragma unroll
                for (int m2 = 0; m2 < 4; m2++)
                    h[m2] = __floats2half2_rn(acc[i][m2 * 2], acc[i][m2 * 2 + 1]);
                *(uint4*)&g_x12h[ob + w0 + tx * 8] = *(uint4*)h;
            }
        }
        __syncthreads();
    }
#endif
}

// ---------------------------------------------------------------------------
// Kernel D (tcgen05 tf32): projection + PReLU.  SINGLE A-buffer (~73KB smem
// -> 3 CTAs/SM), TMEM double buffer.  A staged from fp16 (g_xth / g_x12h).
// Loop: WAIT(t-1) -> stage(t) -> sync -> issue(t) -> epi(t-1) -> sync
// (R13 schedule).  grid (4, 64).
// ---------------------------------------------------------------------------
#define D_SMEM (1024 + 24576 + 49152 + 64)

#if HAS_TCGEN05
static __device__ __forceinline__ void d_stage(
    int tid, int tau, int lbase, int n, int w0, char* pA)
{
    int wq = tau & 7, lb = tau >> 3;
    for (int i = tid; i < 1536; i += 256) {
        int k = i >> 4;               // 0..95
        int lslot = (i >> 1) & 7;
        int h16 = i & 1;
        int hop = k >> 5, c = k & 31;
        int l = lbase + lb * 8 + lslot;
        int lcl = l > 93 ? 93 : l;
        const __half* src;
        if (hop == 0)
            src = g_xth + ((size_t)(n * CIN + c) * LP + lcl) * VP + w0 + wq * 16 + h16 * 8;
        else
            src = g_x12h + ((size_t)(((hop - 1) * N_ + n) * CIN + c) * L_ + lcl) * VP
                  + w0 + wq * 16 + h16 * 8;
        uint4 raw = *(const uint4*)src;           // 8 halves
        const __half2* hp = (const __half2*)&raw;
        unsigned basew = hop * 16384 + SW128(lslot * 128 + (k & 31) * 4);
#pragma unroll
        for (int m = 0; m < 4; m++) {
            float2 f = __half22float2(hp[m]);
            int wsub0 = h16 * 8 + m * 2;
            *(float*)(pA + basew + wsub0 * 1024)       = tf32r(f.x);
            *(float*)(pA + basew + (wsub0 + 1) * 1024) = tf32r(f.y);
        }
    }
}

static __device__ __forceinline__ void d_epilogue(
    int tid, int tau, int lbase, int n, int w0, unsigned tmem,
    const float* sbo, float spa, float* out)
{
    int half = tid >> 7;
    int r = tid & 127;
    int wsub = r >> 3, lslot = r & 7;
    int wq = tau & 7, lb = tau >> 3;
    int l = lbase + lb * 8 + lslot;
    int w = w0 + wq * 16 + wsub;
    unsigned q[32];
    unsigned base = tmem + (tau & 1) * 64 + half * 32;
    ldtm_x32(q, base);
    asm volatile("tcgen05.wait::ld.sync.aligned;" ::: "memory");
    if (w < V_ && l < L_) {
        float* ob = out + (((size_t)n * COUT + half * 32) * V_ + w) * L_ + l;
#pragma unroll
        for (int o = 0; o < 32; o++) {
            float val = __uint_as_float(q[o]) + sbo[half * 32 + o];
            val = val > 0.f ? val : spa * val;
            ob[(size_t)o * V_ * L_] = val;
        }
    }
    asm volatile("tcgen05.fence::before_thread_sync;" ::: "memory");
}
#endif

__global__ __launch_bounds__(256) void kernelD_mma(
    const float* __restrict__ wout,
    const float* __restrict__ bout,
    const float* __restrict__ pa,
    float* __restrict__ out)
{
    int tid = threadIdx.x, wid = tid >> 5;
    int wc = blockIdx.x;
    int n = blockIdx.y >> 1;
    int lhalf = blockIdx.y & 1;
    int lbase = lhalf * 48;
    int w0 = wc * 128;
    __shared__ float sbo[64];
    __shared__ float spa;
    if (tid < 64) sbo[tid] = bout[tid];
    if (tid == 0) spa = pa[0];

#if HAS_TCGEN05
    extern __shared__ char smem[];
    unsigned s0 = smem_u32(smem);
    unsigned sWt = (s0 + 1023) & ~1023u;
    unsigned sA = sWt + 24576;
    unsigned sCtl = sA + 49152;
    char* pWt = smem + (sWt - s0);
    char* pA  = smem + (sA - s0);

    if (wid == 0) {
        asm volatile("tcgen05.alloc.cta_group::1.sync.aligned.shared::cta.b32 [%0], %1;"
                     :: "r"(sCtl), "r"(128) : "memory");
        asm volatile("tcgen05.relinquish_alloc_permit.cta_group::1.sync.aligned;");
    }
    if (tid == 0) {
        asm volatile("mbarrier.init.shared.b64 [%0], %1;" :: "r"(sCtl + 8), "r"(1) : "memory");
        asm volatile("mbarrier.init.shared.b64 [%0], %1;" :: "r"(sCtl + 16), "r"(1) : "memory");
    }

    for (int i = tid; i < 64 * 24; i += 256) {
        int row = i / 24, kq = (i % 24) * 4;
        unsigned off = (kq >> 5) * 8192 + (row >> 3) * 1024 + SW128((row & 7) * 128 + (kq & 31) * 4);
        float4 v = *(const float4*)&wout[row * 96 + kq];
        v.x = tf32r(v.x); v.y = tf32r(v.y); v.z = tf32r(v.z); v.w = tf32r(v.w);
        *(float4*)(pWt + off) = v;
    }
    asm volatile("fence.proxy.async.shared::cta;" ::: "memory");
    __syncthreads();
    unsigned tmem;
    asm volatile("ld.shared.b32 %0, [%1];" : "=r"(tmem) : "r"(sCtl));

    const unsigned idesc = (1u << 4) | (2u << 7) | (2u << 10) | (8u << 17) | (8u << 24);
    unsigned long long wdesc = DESC_BASE | ((unsigned long long)(sWt >> 4) & 0x3FFF);
    unsigned long long adesc = DESC_BASE | ((unsigned long long)(sA >> 4) & 0x3FFF);

    #define D_ISSUE(t) do {                                                    \
        if (wid == 0 && elect_one()) {                                         \
            asm volatile("tcgen05.fence::after_thread_sync;" ::: "memory");    \
            _Pragma("unroll")                                                  \
            for (int s = 0; s < 12; s++) {                                     \
                mma_tf32_ss(tmem + ((t) & 1) * 64,                             \
                            adesc + (unsigned long long)((s >> 2) * 1024 + (s & 3) * 2), \
                            wdesc + (unsigned long long)((s >> 2) * 512 + (s & 3) * 2),  \
                            idesc, s > 0 ? 1u : 0u);                           \
            }                                                                  \
            asm volatile("tcgen05.commit.cta_group::1.mbarrier::arrive::one.shared::cluster.b64 [%0];" \
                         :: "r"(sCtl + 8 + ((t) & 1) * 8) : "memory");         \
        }                                                                      \
    } while (0)

    d_stage(tid, 0, lbase, n, w0, pA);
    asm volatile("fence.proxy.async.shared::cta;" ::: "memory");
    __syncthreads();
    D_ISSUE(0);

    for (int tau = 1; tau < 48; tau++) {
        int tm1 = tau - 1;
        // MMA(tau-1) must be done before overwriting the single A buffer
        mbar_wait_parity(sCtl + 8 + (tm1 & 1) * 8, (unsigned)((tm1 >> 1) & 1));
        asm volatile("tcgen05.fence::after_thread_sync;" ::: "memory");
        d_stage(tid, tau, lbase, n, w0, pA);
        asm volatile("fence.proxy.async.shared::cta;" ::: "memory");
        __syncthreads();
        D_ISSUE(tau);          // overlaps epilogue(tau-1) below
        d_epilogue(tid, tm1, lbase, n, w0, tmem, sbo, spa, out);
        __syncthreads();       // R13 schedule: epilogue done before next iteration
    }
    mbar_wait_parity(sCtl + 8 + (47 & 1) * 8, (unsigned)((47 >> 1) & 1));
    asm volatile("tcgen05.fence::after_thread_sync;" ::: "memory");
    d_epilogue(tid, 47, lbase, n, w0, tmem, sbo, spa, out);
    #undef D_ISSUE

    __syncthreads();
    if (wid == 0)
        asm volatile("tcgen05.dealloc.cta_group::1.sync.aligned.b32 %0, %1;"
                     :: "r"(tmem), "r"(128));
    if (tid == 0) {
        asm volatile("mbarrier.inval.shared.b64 [%0];" :: "r"(sCtl + 8) : "memory");
        asm volatile("mbarrier.inval.shared.b64 [%0];" :: "r"(sCtl + 16) : "memory");
    }
#else
    __syncthreads();
    int lend = (lbase + 48 < 94) ? (lbase + 48) : 94;
    int nl = lend - lbase;
    for (int i = tid; i < 64 * 128 * nl; i += 256) {
        int o = i / (128 * nl);
        int r = i % (128 * nl);
        int wi = r / nl, l = lbase + r % nl;
        int w = w0 + wi;
        if (w < V_) {
            float acc = bout[o];
            for (int k = 0; k < 96; k++) {
                int hop = k >> 5, c = k & 31;
                float h;
                if (hop == 0) h = g_xt[((size_t)(n * CIN + c) * LP + l) * VP + w];
                else h = g_x12[((size_t)(((hop - 1) * N_ + n) * CIN + c) * L_ + l) * VP + w];
                acc = fmaf(wout[o * 96 + k], h, acc);
            }
            acc = acc > 0.f ? acc : spa * acc;
            out[(((size_t)n * COUT + o) * V_ + w) * L_ + l] = acc;
        }
    }
#endif
}

// ---------------------------------------------------------------------------
extern "C" void kernel_launch(void* const* d_in, const int* in_sizes, int n_in,
                              void* d_out, int out_size) {
    const float* x    = (const float*)d_in[0];
    const float* A    = (const float*)d_in[1];
    const float* w1   = (const float*)d_in[2];
    const float* b1   = (const float*)d_in[3];
    const float* w2   = (const float*)d_in[4];
    const float* b2   = (const float*)d_in[5];
    const float* w3   = (const float*)d_in[6];
    const float* b3   = (const float*)d_in[7];
    const float* wout = (const float*)d_in[8];
    const float* bout = (const float*)d_in[9];
    const float* pa   = (const float*)d_in[10];
    float* out = (float*)d_out;

    cudaFuncSetAttribute(kernelC,     cudaFuncAttributeMaxDynamicSharedMemorySize, C_SMEM_BYTES);
    cudaFuncSetAttribute(kernelB_mma, cudaFuncAttributeMaxDynamicSharedMemorySize, BM_SMEM);
    cudaFuncSetAttribute(kernelD_mma, cudaFuncAttributeMaxDynamicSharedMemorySize, D_SMEM);
    cudaFuncSetAttribute(kernelX,     cudaFuncAttributeMaxDynamicSharedMemorySize, X_SMEM);

    kernelA<<<dim3(32, 32), dim3(16, 16)>>>(A);
    kernelW<<<48, 256>>>(w1, w2, w3);
    kernelX<<<dim3(125, 32), 256, X_SMEM>>>(x);
    kernelB_mma<<<dim3(4, 64), 256, BM_SMEM>>>(b1, b2, b3);
    kernelC<<<dim3(4, 24, 32), 256, C_SMEM_BYTES>>>();
    kernelD_mma<<<dim3(4, 64), 256, D_SMEM>>>(wout, bout, pa, out);
}

// round 17
// speedup vs baseline: 1.2043x; 1.1761x over previous
#include <cuda_runtime.h>
#include <cuda_bf16.h>
#include <cuda_fp16.h>

#define N_    32
#define CIN   32
#define V_    500
#define T_    96
#define L_    94      // T - K + 1
#define COUT  64
#define VP    512     // padded v/w dim
#define LP    96      // padded l dim in g_xt

// Scratch (zero-initialized at module load; padding regions never written)
__device__ float          g_xt  [N_ * CIN * LP * VP];     // fp32 (fallback only)
__device__ __half         g_xth [N_ * CIN * LP * VP];     // fp16 xt (for kernelD hop0)
__device__ __nv_bfloat16  g_xtb [N_ * CIN * LP * VP];     // bf16 xt (for kernelC)
__device__ float          g_x12 [2 * N_ * CIN * L_ * VP]; // fp32 (fallback only)
__device__ __half         g_x12h[2 * N_ * CIN * L_ * VP]; // fp16 x1/x2 (for kernelD)
__device__ float          g_Apad [VP * VP];               // fallback
__device__ float          g_A2pad[VP * VP];               // fallback
__device__ __nv_bfloat16  g_ATb [VP * VP];                // A^T
__device__ __nv_bfloat16  g_A2Tb[VP * VP];                // (A@A)^T
// xp, pre-swizzled: [n][vc=4][t=96] blocks of 4096 floats; elem (vr,ci) at SW128(vr*128+ci*4)
__device__ float          g_xpsw[N_ * 4 * T_ * 4096];
// stacked conv weights, INTERLEAVED: row = c*4 + j (j=0,1,2 conv; j=3 zero)
__device__ float          g_Wcat[128 * 96];

#define HAS_TCGEN05 (defined(__CUDA_ARCH_FEAT_SM103_ALL) || defined(__CUDA_ARCH_FEAT_SM100_ALL) || defined(__CUDA_ARCH_FEAT_SM101_ALL))

#define SW128(o) ((o) ^ (((o) >> 3) & 0x70))

static __device__ __forceinline__ unsigned smem_u32(const void* p) {
    unsigned a;
    asm("{ .reg .u64 t; cvta.to.shared.u64 t, %1; cvt.u32.u64 %0, t; }"
        : "=r"(a) : "l"(p));
    return a;
}

static __device__ __forceinline__ float tf32r(float x) {
    float r;
    asm("cvt.rna.tf32.f32 %0, %1;" : "=f"(r) : "f"(x));
    return r;
}

#if HAS_TCGEN05
static __device__ __forceinline__ unsigned elect_one() {
    unsigned p;
    asm volatile("{\n\t.reg .pred p;\n\telect.sync _|p, 0xFFFFFFFF;\n\t"
                 "selp.b32 %0, 1, 0, p;\n\t}" : "=r"(p));
    return p;
}

static __device__ __forceinline__ void mbar_wait_parity(unsigned mbar, unsigned phase) {
    asm volatile(
        "{\n\t.reg .pred P1;\n\t"
        "WL_%=:\n\t"
        "mbarrier.try_wait.parity.acquire.cta.shared::cta.b64 P1, [%0], %1, 0x989680;\n\t"
        "@P1 bra.uni WD_%=;\n\t"
        "bra.uni WL_%=;\n\t"
        "WD_%=:\n\t}"
        :: "r"(mbar), "r"(phase) : "memory");
}

static __device__ __forceinline__ void mma_bf16_ss(unsigned d_tmem, unsigned long long a_desc,
                                                   unsigned long long b_desc, unsigned idesc,
                                                   unsigned en) {
    asm volatile(
        "{\n\t.reg .pred p;\n\t"
        "setp.ne.u32 p, %4, 0;\n\t"
        "tcgen05.mma.cta_group::1.kind::f16 [%0], %1, %2, %3, {%5, %5, %5, %5}, p;\n\t}"
        :: "r"(d_tmem), "l"(a_desc), "l"(b_desc), "r"(idesc), "r"(en), "r"(0u)
        : "memory");
}

static __device__ __forceinline__ void mma_tf32_ss(unsigned d_tmem, unsigned long long a_desc,
                                                   unsigned long long b_desc, unsigned idesc,
                                                   unsigned en) {
    asm volatile(
        "{\n\t.reg .pred p;\n\t"
        "setp.ne.u32 p, %4, 0;\n\t"
        "tcgen05.mma.cta_group::1.kind::tf32 [%0], %1, %2, %3, {%5, %5, %5, %5}, p;\n\t}"
        :: "r"(d_tmem), "l"(a_desc), "l"(b_desc), "r"(idesc), "r"(en), "r"(0u)
        : "memory");
}

static __device__ __forceinline__ void ldtm_x32(unsigned* r, unsigned addr) {
    asm volatile(
        "tcgen05.ld.sync.aligned.32x32b.x32.b32 "
        "{%0, %1, %2, %3, %4, %5, %6, %7, "
        " %8, %9, %10, %11, %12, %13, %14, %15, "
        " %16, %17, %18, %19, %20, %21, %22, %23, "
        " %24, %25, %26, %27, %28, %29, %30, %31}, [%32];"
        : "=r"(r[0]),  "=r"(r[1]),  "=r"(r[2]),  "=r"(r[3]),
          "=r"(r[4]),  "=r"(r[5]),  "=r"(r[6]),  "=r"(r[7]),
          "=r"(r[8]),  "=r"(r[9]),  "=r"(r[10]), "=r"(r[11]),
          "=r"(r[12]), "=r"(r[13]), "=r"(r[14]), "=r"(r[15]),
          "=r"(r[16]), "=r"(r[17]), "=r"(r[18]), "=r"(r[19]),
          "=r"(r[20]), "=r"(r[21]), "=r"(r[22]), "=r"(r[23]),
          "=r"(r[24]), "=r"(r[25]), "=r"(r[26]), "=r"(r[27]),
          "=r"(r[28]), "=r"(r[29]), "=r"(r[30]), "=r"(r[31])
        : "r"(addr));
}

#define DESC_BASE ((2ULL << 61) | (1ULL << 46) | (64ULL << 32) | (1ULL << 16))
#endif  // HAS_TCGEN05

// ---------------------------------------------------------------------------
// Kernel A: A@A; emit fp32 padded (fallback) + bf16 transposed
// ---------------------------------------------------------------------------
__global__ __launch_bounds__(256) void kernelA(const float* __restrict__ A) {
    __shared__ float As[16][16];
    __shared__ float Bs[16][16];
    int tx = threadIdx.x, ty = threadIdx.y;
    int w = blockIdx.x * 16 + tx;
    int v = blockIdx.y * 16 + ty;
    float aval = (v < V_ && w < V_) ? A[v * V_ + w] : 0.f;
    float acc = 0.f;
    for (int u0 = 0; u0 < V_; u0 += 16) {
        int u1 = u0 + tx, u2 = u0 + ty;
        As[ty][tx] = (v < V_ && u1 < V_) ? A[v * V_ + u1] : 0.f;
        Bs[ty][tx] = (u2 < V_ && w < V_) ? A[u2 * V_ + w] : 0.f;
        __syncthreads();
#pragma unroll
        for (int u = 0; u < 16; u++) acc += As[ty][u] * Bs[u][tx];
        __syncthreads();
    }
    float a2val = (v < V_ && w < V_) ? acc : 0.f;
    g_Apad [v * VP + w] = aval;
    g_A2pad[v * VP + w] = a2val;
    g_ATb [w * VP + v] = __float2bfloat16(aval);
    g_A2Tb[w * VP + v] = __float2bfloat16(a2val);
}

// ---------------------------------------------------------------------------
// Kernel W: interleaved Wcat: row = c*4 + j; col k' = kk*32 + ci (tf32)
// ---------------------------------------------------------------------------
__global__ __launch_bounds__(256) void kernelW(
    const float* __restrict__ w1, const float* __restrict__ w2,
    const float* __restrict__ w3)
{
    int idx = blockIdx.x * 256 + threadIdx.x;
    if (idx < 128 * 96) {
        int row = idx / 96, kp = idx % 96;
        int c = row >> 2, j = row & 3;
        int kk = kp >> 5, ci = kp & 31;
        float val = 0.f;
        if (j == 0)      val = w1[c * 96 + ci * 3 + kk];
        else if (j == 1) val = w2[c * 96 + ci * 3 + kk];
        else if (j == 2) val = w3[c * 96 + ci * 3 + kk];
        g_Wcat[idx] = tf32r(val);
    }
}

// ---------------------------------------------------------------------------
// Kernel X: x[n][ci][v][t] -> g_xpsw swizzled atom-col blocks (tf32-rounded)
// ---------------------------------------------------------------------------
#define X_SMEM (4 * 96 * 33 * 4)
__global__ __launch_bounds__(256) void kernelX(const float* __restrict__ x) {
    extern __shared__ float xs[];          // [vt][33]
    int v0 = blockIdx.x * 4, n = blockIdx.y;
    int tid = threadIdx.x;
    for (int i = tid; i < CIN * 4 * T_; i += 256) {
        int t  = i % T_;
        int r  = i / T_;
        int vi = r & 3;
        int ci = r >> 2;
        xs[(vi * T_ + t) * 33 + ci] = x[((n * CIN + ci) * V_ + v0 + vi) * T_ + t];
    }
    __syncthreads();
    for (int i = tid; i < 3072; i += 256) {
        int ci4 = i & 7;
        int r   = i >> 3;            // vi*96 + t
        int t   = r % 96;
        int vi  = r / 96;
        const float* s = &xs[r * 33 + ci4 * 4];
        float4 o;
        o.x = tf32r(s[0]); o.y = tf32r(s[1]); o.z = tf32r(s[2]); o.w = tf32r(s[3]);
        int v = v0 + vi, vc = v >> 7, vr = v & 127;
        *(float4*)&g_xpsw[((size_t)(n * 4 + vc) * T_ + t) * 4096
                          + (SW128(vr * 128 + ci4 * 16) >> 2)] = o;
    }
}

// ---------------------------------------------------------------------------
// Kernel B (tcgen05 tf32): pipelined, 2 CTAs/SM (ring of 3 t-cols, ~97KB smem).
// Per CTA (vc, n, lhalf).  1-l batches, TMEM 256 cols (2 buf x 128).
// Loop: WAIT(i-1) -> STAGE(i) -> sync -> ISSUE(i) -> EPI(i-1) -> sync
// (R13 schedule).  Epilogue over all 8 warps, BOTH LDTMs issued before one
// wait (latency fix); emits fp16 g_xth + bf16 g_xtb.
// grid (4, 64), 256 threads.
// ---------------------------------------------------------------------------
#define BRING 3
#define BM_SMEM (1024 + 49152 + BRING * 16384 + 64)

__global__ __launch_bounds__(256) void kernelB_mma(
    const float* __restrict__ b1, const float* __restrict__ b2,
    const float* __restrict__ b3)
{
    int tid = threadIdx.x, wid = tid >> 5;
    int vc = blockIdx.x;
    int n = blockIdx.y >> 1;
    int lhalf = blockIdx.y & 1;
    int lbase = lhalf * 48;
    int lend  = (lbase + 48 < 94) ? (lbase + 48) : 94;
    int v0 = vc * 128;
    __shared__ float sb[96];
    if (tid < 96) sb[tid] = (tid < 32) ? b1[tid] : (tid < 64) ? b2[tid - 32] : b3[tid - 64];

#if HAS_TCGEN05
    extern __shared__ char smem[];
    unsigned s0 = smem_u32(smem);
    unsigned sW = (s0 + 1023) & ~1023u;
    unsigned sR = sW + 49152;
    unsigned sCtl = sR + BRING * 16384;   // [0:4) tmem, [8:16) mbar0, [16:24) mbar1
    char* pW = smem + (sW - s0);
    char* pR = smem + (sR - s0);

    if (wid == 0) {
        asm volatile("tcgen05.alloc.cta_group::1.sync.aligned.shared::cta.b32 [%0], %1;"
                     :: "r"(sCtl), "r"(256) : "memory");
        asm volatile("tcgen05.relinquish_alloc_permit.cta_group::1.sync.aligned;");
    }
    if (tid == 0) {
        asm volatile("mbarrier.init.shared.b64 [%0], %1;" :: "r"(sCtl + 8), "r"(1) : "memory");
        asm volatile("mbarrier.init.shared.b64 [%0], %1;" :: "r"(sCtl + 16), "r"(1) : "memory");
    }

    for (int i = tid; i < 128 * 24; i += 256) {
        int row = i / 24, kq = (i % 24) * 4;
        unsigned off = (kq >> 5) * 16384 + (row >> 3) * 1024 + SW128((row & 7) * 128 + (kq & 31) * 4);
        *(float4*)(pW + off) = *(const float4*)&g_Wcat[row * 96 + kq];
    }
    __syncthreads();
    unsigned tmem;
    asm volatile("ld.shared.b32 %0, [%1];" : "=r"(tmem) : "r"(sCtl));

    const unsigned idesc = (1u << 4) | (2u << 7) | (2u << 10) | (16u << 17) | (8u << 24);
    unsigned long long wdesc = DESC_BASE | ((unsigned long long)(sW >> 4) & 0x3FFF);
    unsigned long long rdesc = DESC_BASE | ((unsigned long long)(sR >> 4) & 0x3FFF);

    const float* xbase = g_xpsw + (size_t)(n * 4 + vc) * T_ * 4096;
    int tcap = (lend + 2 < 96) ? (lend + 2) : 96;
    int nb = lend - lbase;              // 1-l batches
    int staged = lbase;

    #define B_STAGE(i) do {                                                    \
        int tgt = lbase + (i) + 3; if (tgt > tcap) tgt = tcap;                 \
        for (; staged < tgt; staged++) {                                       \
            const float4* src = (const float4*)(xbase + (size_t)staged * 4096);\
            float4* dst = (float4*)(pR + (staged % 3) * 16384);                \
            for (int j = tid; j < 1024; j += 256) dst[j] = src[j];             \
        }                                                                      \
        asm volatile("fence.proxy.async.shared::cta;" ::: "memory");           \
    } while (0)

    #define B_ISSUE(i) do {                                                    \
        if (wid == 0 && elect_one()) {                                         \
            asm volatile("tcgen05.fence::after_thread_sync;" ::: "memory");    \
            int l = lbase + (i);                                               \
            _Pragma("unroll")                                                  \
            for (int s = 0; s < 12; s++) {                                     \
                unsigned long long ad = rdesc +                                \
                    (unsigned long long)(((l + (s >> 2)) % 3) * 1024 + (s & 3) * 2); \
                unsigned long long bd = wdesc +                                \
                    (unsigned long long)((s >> 2) * 1024 + (s & 3) * 2);       \
                mma_tf32_ss(tmem + ((i) & 1) * 128, ad, bd, idesc, s > 0 ? 1u : 0u); \
            }                                                                  \
            asm volatile("tcgen05.commit.cta_group::1.mbarrier::arrive::one.shared::cluster.b64 [%0];" \
                         :: "r"(sCtl + 8 + ((i) & 1) * 8) : "memory");         \
        }                                                                      \
    } while (0)

    #define B_WAIT(jb) do {                                                    \
        mbar_wait_parity(sCtl + 8 + ((jb) & 1) * 8, (unsigned)(((jb) >> 1) & 1)); \
        asm volatile("tcgen05.fence::after_thread_sync;" ::: "memory");        \
    } while (0)

    // epilogue batch jb: 8 warps; both LDTMs issued before ONE wait
    #define B_EPI(jb) do {                                                     \
        {                                                                      \
            int half = tid >> 7;                                               \
            int v = v0 + (tid & 127);                                          \
            int l = lbase + (jb);                                              \
            unsigned tb = tmem + ((jb) & 1) * 128;                             \
            unsigned qa[32], qb[32];                                           \
            ldtm_x32(qa, tb + (half * 2 + 0) * 32);                            \
            ldtm_x32(qb, tb + (half * 2 + 1) * 32);                            \
            asm volatile("tcgen05.wait::ld.sync.aligned;" ::: "memory");       \
            if (v < V_) {                                                      \
                _Pragma("unroll")                                              \
                for (int gi = 0; gi < 2; gi++) {                               \
                    const unsigned* q = gi ? qb : qa;                          \
                    int g = half * 2 + gi;                                     \
                    _Pragma("unroll")                                          \
                    for (int cc = 0; cc < 8; cc++) {                           \
                        int c = g * 8 + cc;                                    \
                        float t1 = __uint_as_float(q[cc * 4 + 0]) + sb[c];      \
                        float t2 = __uint_as_float(q[cc * 4 + 1]) + sb[32 + c]; \
                        float t3 = __uint_as_float(q[cc * 4 + 2]) + sb[64 + c]; \
                        float r = t1 + 1.f / (1.f + __expf(-t2)) + t3;         \
                        r = fmaxf(r, 0.f);                                     \
                        int idx = ((n * CIN + c) * LP + l) * VP + v;           \
                        g_xth[idx] = __float2half_rn(r);                       \
                        g_xtb[idx] = __float2bfloat16(r);                      \
                    }                                                          \
                }                                                              \
            }                                                                  \
            asm volatile("tcgen05.fence::before_thread_sync;" ::: "memory");   \
        }                                                                      \
    } while (0)

    B_STAGE(0);
    __syncthreads();
    B_ISSUE(0);
    for (int i = 1; i < nb; i++) {
        B_WAIT(i - 1);         // MMA(i-1) done -> ring slot of col i-1 reusable
        B_STAGE(i);
        __syncthreads();
        B_ISSUE(i);            // overlaps epilogue body below
        B_EPI(i - 1);
        __syncthreads();       // epilogue done before next iteration's ISSUE reuses TMEM
    }
    B_WAIT(nb - 1);
    B_EPI(nb - 1);
    __syncthreads();

    if (wid == 0)
        asm volatile("tcgen05.dealloc.cta_group::1.sync.aligned.b32 %0, %1;"
                     :: "r"(tmem), "r"(256));
    if (tid == 0) {
        asm volatile("mbarrier.inval.shared.b64 [%0];" :: "r"(sCtl + 8) : "memory");
        asm volatile("mbarrier.inval.shared.b64 [%0];" :: "r"(sCtl + 16) : "memory");
    }
    #undef B_STAGE
    #undef B_ISSUE
    #undef B_WAIT
    #undef B_EPI
#else
    __syncthreads();
    for (int i = tid; i < (lend - lbase) * 32 * 128; i += 256) {
        int l = lbase + i / (32 * 128);
        int r = i % (32 * 128);
        int c = r >> 7, vi = r & 127;
        int v = v0 + vi;
        if (v < V_) {
            float a1 = 0.f, a2 = 0.f, a3 = 0.f;
            for (int k = 0; k < 96; k++) {
                int kk = k >> 5, ci = k & 31;
                float xv = g_xpsw[((size_t)(n * 4 + vc) * T_ + l + kk) * 4096
                                  + (SW128(vi * 128 + ci * 4) >> 2)];
                a1 = fmaf(g_Wcat[(c * 4 + 0) * 96 + k], xv, a1);
                a2 = fmaf(g_Wcat[(c * 4 + 1) * 96 + k], xv, a2);
                a3 = fmaf(g_Wcat[(c * 4 + 2) * 96 + k], xv, a3);
            }
            float r2 = (a1 + sb[c]) + 1.f / (1.f + __expf(-(a2 + sb[32 + c]))) + (a3 + sb[64 + c]);
            r2 = fmaxf(r2, 0.f);
            int idx = ((n * CIN + c) * LP + l) * VP + v;
            g_xt [idx] = r2;
            g_xtb[idx] = __float2bfloat16(r2);
            g_xth[idx] = __float2half_rn(r2);
        }
    }
#endif
}

// ---------------------------------------------------------------------------
// Kernel C: diffusion GEMM — bf16 tcgen05, A-tile reused across 2 w-tiles,
// register prefetch, 2 CTAs/SM.  grid (4, 24, 32): x = mat*2 + whalf,
// y = m-tile, z = n.  256 threads.  Epilogue emits fp16 g_x12h.
// (R13 version, unchanged)
// ---------------------------------------------------------------------------
#define C_SMEM_BYTES (80 * 1024)

__global__ __launch_bounds__(256) void kernelC() {
    extern __shared__ char smem[];
    __shared__ int rowbase[128];
    __shared__ int obase[128];

    int tid = threadIdx.x, wid = tid >> 5, lid = tid & 31;
    int mat = blockIdx.x >> 1;
    int wh  = blockIdx.x & 1;
    int m0  = blockIdx.y * 128;
    int n   = blockIdx.z;

    if (tid < 128) {
        int m = m0 + tid;
        bool valid = m < CIN * L_;
        int mm = valid ? m : 0;
        int c = mm / L_, l = mm % L_;
        rowbase[tid] = ((n * CIN + c) * LP + l) * VP;
        obase[tid]   = valid ? ((((mat * N_ + n) * CIN + c) * L_ + l) * VP) : -1;
    }

#if HAS_TCGEN05
    unsigned s0 = smem_u32(smem);
    unsigned sA = (s0 + 1023) & ~1023u;
    unsigned sB0 = sA + 16384;
    unsigned sB1 = sB0 + 16384;
    unsigned sCtl = sB1 + 16384;
    char* pA  = smem + (sA - s0);
    char* pB0 = smem + (sB0 - s0);
    char* pB1 = smem + (sB1 - s0);
    const __nv_bfloat16* __restrict__ Bm = mat ? g_A2Tb : g_ATb;

    if (wid == 0) {
        asm volatile("tcgen05.alloc.cta_group::1.sync.aligned.shared::cta.b32 [%0], %1;"
                     :: "r"(sCtl), "r"(256) : "memory");
        asm volatile("tcgen05.relinquish_alloc_permit.cta_group::1.sync.aligned;");
    }
    if (tid == 0)
        asm volatile("mbarrier.init.shared.b64 [%0], %1;" :: "r"(sCtl + 8), "r"(1) : "memory");
    __syncthreads();
    unsigned tmem;
    asm volatile("ld.shared.b32 %0, [%1];" : "=r"(tmem) : "r"(sCtl));

    const unsigned idesc = 0x490u | (16u << 17) | (8u << 24);
    unsigned long long adesc  = DESC_BASE | ((unsigned long long)(sA  >> 4) & 0x3FFF);
    unsigned long long b0desc = DESC_BASE | ((unsigned long long)(sB0 >> 4) & 0x3FFF);
    unsigned long long b1desc = DESC_BASE | ((unsigned long long)(sB1 >> 4) & 0x3FFF);

    const __nv_bfloat16* pa4[4];
    const __nv_bfloat16* pb0[4];
    const __nv_bfloat16* pb1[4];
    unsigned swo[4];
#pragma unroll
    for (int it = 0; it < 4; it++) {
        int idx = tid + it * 256;
        int row = idx >> 3, c16 = idx & 7;
        swo[it] = SW128((unsigned)(row * 128 + c16 * 16));
        pa4[it] = &g_xtb[rowbase[row] + c16 * 8];
        pb0[it] = &Bm[(wh * 256 + row) * VP + c16 * 8];
        pb1[it] = &Bm[(wh * 256 + 128 + row) * VP + c16 * 8];
    }
    float4 va[4], vb0[4], vb1[4];
#pragma unroll
    for (int it = 0; it < 4; it++) {
        va[it]  = *(const float4*)pa4[it];
        vb0[it] = *(const float4*)pb0[it];
        vb1[it] = *(const float4*)pb1[it];
    }

    for (int kc = 0; kc < 8; kc++) {
#pragma unroll
        for (int it = 0; it < 4; it++) {
            *(float4*)(pA  + swo[it]) = va[it];
            *(float4*)(pB0 + swo[it]) = vb0[it];
            *(float4*)(pB1 + swo[it]) = vb1[it];
        }
        asm volatile("fence.proxy.async.shared::cta;" ::: "memory");
        __syncthreads();
        if (wid == 0 && elect_one()) {
#pragma unroll
            for (int j = 0; j < 4; j++)
                mma_bf16_ss(tmem, adesc + j * 2, b0desc + j * 2, idesc,
                            (kc > 0 || j > 0) ? 1u : 0u);
#pragma unroll
            for (int j = 0; j < 4; j++)
                mma_bf16_ss(tmem + 128, adesc + j * 2, b1desc + j * 2, idesc,
                            (kc > 0 || j > 0) ? 1u : 0u);
            asm volatile(
                "tcgen05.commit.cta_group::1.mbarrier::arrive::one.shared::cluster.b64 [%0];"
                :: "r"(sCtl + 8) : "memory");
        }
        if (kc < 7) {
            int k1 = (kc + 1) * 64;
#pragma unroll
            for (int it = 0; it < 4; it++) {
                va[it]  = *(const float4*)(pa4[it] + k1);
                vb0[it] = *(const float4*)(pb0[it] + k1);
                vb1[it] = *(const float4*)(pb1[it] + k1);
            }
        }
        mbar_wait_parity(sCtl + 8, (unsigned)(kc & 1));
    }

    asm volatile("tcgen05.fence::after_thread_sync;" ::: "memory");

    if (wid < 4) {
        int row = wid * 32 + lid;
        int ob = obase[row];
#pragma unroll
        for (int acc = 0; acc < 2; acc++) {
#pragma unroll
            for (int g = 0; g < 4; g++) {
                unsigned r[32];
                ldtm_x32(r, tmem + acc * 128 + g * 32);
                asm volatile("tcgen05.wait::ld.sync.aligned;" ::: "memory");
                if (ob >= 0) {
#pragma unroll
                    for (int q = 0; q < 4; q++) {       // 8 cols per 16B store
                        __half2 h[4];
#pragma unroll
                        for (int m = 0; m < 4; m++)
                            h[m] = __floats2half2_rn(
                                __uint_as_float(r[q * 8 + m * 2]),
                                __uint_as_float(r[q * 8 + m * 2 + 1]));
                        *(uint4*)&g_x12h[ob + wh * 256 + acc * 128 + g * 32 + q * 8]
                            = *(uint4*)h;
                    }
                }
            }
        }
    }
    __syncthreads();
    if (tid == 0)
        asm volatile("mbarrier.inval.shared.b64 [%0];" :: "r"(sCtl + 8) : "memory");
    if (wid == 0)
        asm volatile("tcgen05.dealloc.cta_group::1.sync.aligned.b32 %0, %1;"
                     :: "r"(tmem), "r"(256));
#else
    (void)wid; (void)lid;
    float* As = (float*)smem;
    float* Bs = As + 16 * 132;
    const float* __restrict__ Bmf = mat ? g_A2pad : g_Apad;
    __syncthreads();
    int ty = tid >> 4, tx = tid & 15;
    for (int wsel = 0; wsel < 2; wsel++) {
        int w0 = wh * 256 + wsel * 128;
        float acc[8][8] = {};
        for (int k0 = 0; k0 < VP; k0 += 16) {
            __syncthreads();
#pragma unroll
            for (int it = 0; it < 2; it++) {
                int i = tid + it * 256;
                int arow = i >> 2, aq = i & 3;
                float4 va2 = *(const float4*)&g_xt[rowbase[arow] + k0 + aq * 4];
                As[(aq * 4 + 0) * 132 + arow] = va2.x;
                As[(aq * 4 + 1) * 132 + arow] = va2.y;
                As[(aq * 4 + 2) * 132 + arow] = va2.z;
                As[(aq * 4 + 3) * 132 + arow] = va2.w;
                int bk = i >> 5, bw = (i & 31) * 4;
                float4 vb2 = *(const float4*)&Bmf[(k0 + bk) * VP + w0 + bw];
                *(float4*)&Bs[bk * 132 + bw] = vb2;
            }
            __syncthreads();
#pragma unroll
            for (int kk = 0; kk < 16; kk++) {
                float4 a0 = *(const float4*)&As[kk * 132 + ty * 8];
                float4 a1 = *(const float4*)&As[kk * 132 + ty * 8 + 4];
                float4 b0 = *(const float4*)&Bs[kk * 132 + tx * 8];
                float4 b1v = *(const float4*)&Bs[kk * 132 + tx * 8 + 4];
                float ar[8] = {a0.x, a0.y, a0.z, a0.w, a1.x, a1.y, a1.z, a1.w};
                float br[8] = {b0.x, b0.y, b0.z, b0.w, b1v.x, b1v.y, b1v.z, b1v.w};
#pragma unroll
                for (int i = 0; i < 8; i++)
#pragma unroll
                    for (int j = 0; j < 8; j++)
                        acc[i][j] = fmaf(ar[i], br[j], acc[i][j]);
            }
        }
#pragma unroll
        for (int i = 0; i < 8; i++) {
            int ob = obase[ty * 8 + i];
            if (ob >= 0) {
                *(float4*)&g_x12[ob + w0 + tx * 8]     = make_float4(acc[i][0], acc[i][1], acc[i][2], acc[i][3]);
                *(float4*)&g_x12[ob + w0 + tx * 8 + 4] = make_float4(acc[i][4], acc[i][5], acc[i][6], acc[i][7]);
                __half2 h[4];
#pragma unroll
                for (int m2 = 0; m2 < 4; m2++)
                    h[m2] = __floats2half2_rn(acc[i][m2 * 2], acc[i][m2 * 2 + 1]);
                *(uint4*)&g_x12h[ob + w0 + tx * 8] = *(uint4*)h;
            }
        }
        __syncthreads();
    }
#endif
}

// ---------------------------------------------------------------------------
// Kernel D (tcgen05 tf32): projection + PReLU.  SINGLE A-buffer (~73KB smem
// -> 3 CTAs/SM), TMEM double buffer.  A staged from fp16 (g_xth / g_x12h).
// Loop: WAIT(t-1) -> stage(t) -> sync -> issue(t) -> epi(t-1) -> sync
// (R13 schedule).  grid (4, 64).  (R13 version, unchanged)
// ---------------------------------------------------------------------------
#define D_SMEM (1024 + 24576 + 49152 + 64)

#if HAS_TCGEN05
static __device__ __forceinline__ void d_stage(
    int tid, int tau, int lbase, int n, int w0, char* pA)
{
    int wq = tau & 7, lb = tau >> 3;
    for (int i = tid; i < 1536; i += 256) {
        int k = i >> 4;               // 0..95
        int lslot = (i >> 1) & 7;
        int h16 = i & 1;
        int hop = k >> 5, c = k & 31;
        int l = lbase + lb * 8 + lslot;
        int lcl = l > 93 ? 93 : l;
        const __half* src;
        if (hop == 0)
            src = g_xth + ((size_t)(n * CIN + c) * LP + lcl) * VP + w0 + wq * 16 + h16 * 8;
        else
            src = g_x12h + ((size_t)(((hop - 1) * N_ + n) * CIN + c) * L_ + lcl) * VP
                  + w0 + wq * 16 + h16 * 8;
        uint4 raw = *(const uint4*)src;           // 8 halves
        const __half2* hp = (const __half2*)&raw;
        unsigned basew = hop * 16384 + SW128(lslot * 128 + (k & 31) * 4);
#pragma unroll
        for (int m = 0; m < 4; m++) {
            float2 f = __half22float2(hp[m]);
            int wsub0 = h16 * 8 + m * 2;
            *(float*)(pA + basew + wsub0 * 1024)       = tf32r(f.x);
            *(float*)(pA + basew + (wsub0 + 1) * 1024) = tf32r(f.y);
        }
    }
}

static __device__ __forceinline__ void d_epilogue(
    int tid, int tau, int lbase, int n, int w0, unsigned tmem,
    const float* sbo, float spa, float* out)
{
    int half = tid >> 7;
    int r = tid & 127;
    int wsub = r >> 3, lslot = r & 7;
    int wq = tau & 7, lb = tau >> 3;
    int l = lbase + lb * 8 + lslot;
    int w = w0 + wq * 16 + wsub;
    unsigned q[32];
    unsigned base = tmem + (tau & 1) * 64 + half * 32;
    ldtm_x32(q, base);
    asm volatile("tcgen05.wait::ld.sync.aligned;" ::: "memory");
    if (w < V_ && l < L_) {
        float* ob = out + (((size_t)n * COUT + half * 32) * V_ + w) * L_ + l;
#pragma unroll
        for (int o = 0; o < 32; o++) {
            float val = __uint_as_float(q[o]) + sbo[half * 32 + o];
            val = val > 0.f ? val : spa * val;
            ob[(size_t)o * V_ * L_] = val;
        }
    }
    asm volatile("tcgen05.fence::before_thread_sync;" ::: "memory");
}
#endif

__global__ __launch_bounds__(256) void kernelD_mma(
    const float* __restrict__ wout,
    const float* __restrict__ bout,
    const float* __restrict__ pa,
    float* __restrict__ out)
{
    int tid = threadIdx.x, wid = tid >> 5;
    int wc = blockIdx.x;
    int n = blockIdx.y >> 1;
    int lhalf = blockIdx.y & 1;
    int lbase = lhalf * 48;
    int w0 = wc * 128;
    __shared__ float sbo[64];
    __shared__ float spa;
    if (tid < 64) sbo[tid] = bout[tid];
    if (tid == 0) spa = pa[0];

#if HAS_TCGEN05
    extern __shared__ char smem[];
    unsigned s0 = smem_u32(smem);
    unsigned sWt = (s0 + 1023) & ~1023u;
    unsigned sA = sWt + 24576;
    unsigned sCtl = sA + 49152;
    char* pWt = smem + (sWt - s0);
    char* pA  = smem + (sA - s0);

    if (wid == 0) {
        asm volatile("tcgen05.alloc.cta_group::1.sync.aligned.shared::cta.b32 [%0], %1;"
                     :: "r"(sCtl), "r"(128) : "memory");
        asm volatile("tcgen05.relinquish_alloc_permit.cta_group::1.sync.aligned;");
    }
    if (tid == 0) {
        asm volatile("mbarrier.init.shared.b64 [%0], %1;" :: "r"(sCtl + 8), "r"(1) : "memory");
        asm volatile("mbarrier.init.shared.b64 [%0], %1;" :: "r"(sCtl + 16), "r"(1) : "memory");
    }

    for (int i = tid; i < 64 * 24; i += 256) {
        int row = i / 24, kq = (i % 24) * 4;
        unsigned off = (kq >> 5) * 8192 + (row >> 3) * 1024 + SW128((row & 7) * 128 + (kq & 31) * 4);
        float4 v = *(const float4*)&wout[row * 96 + kq];
        v.x = tf32r(v.x); v.y = tf32r(v.y); v.z = tf32r(v.z); v.w = tf32r(v.w);
        *(float4*)(pWt + off) = v;
    }
    asm volatile("fence.proxy.async.shared::cta;" ::: "memory");
    __syncthreads();
    unsigned tmem;
    asm volatile("ld.shared.b32 %0, [%1];" : "=r"(tmem) : "r"(sCtl));

    const unsigned idesc = (1u << 4) | (2u << 7) | (2u << 10) | (8u << 17) | (8u << 24);
    unsigned long long wdesc = DESC_BASE | ((unsigned long long)(sWt >> 4) & 0x3FFF);
    unsigned long long adesc = DESC_BASE | ((unsigned long long)(sA >> 4) & 0x3FFF);

    #define D_ISSUE(t) do {                                                    \
        if (wid == 0 && elect_one()) {                                         \
            asm volatile("tcgen05.fence::after_thread_sync;" ::: "memory");    \
            _Pragma("unroll")                                                  \
            for (int s = 0; s < 12; s++) {                                     \
                mma_tf32_ss(tmem + ((t) & 1) * 64,                             \
                            adesc + (unsigned long long)((s >> 2) * 1024 + (s & 3) * 2), \
                            wdesc + (unsigned long long)((s >> 2) * 512 + (s & 3) * 2),  \
                            idesc, s > 0 ? 1u : 0u);                           \
            }                                                                  \
            asm volatile("tcgen05.commit.cta_group::1.mbarrier::arrive::one.shared::cluster.b64 [%0];" \
                         :: "r"(sCtl + 8 + ((t) & 1) * 8) : "memory");         \
        }                                                                      \
    } while (0)

    d_stage(tid, 0, lbase, n, w0, pA);
    asm volatile("fence.proxy.async.shared::cta;" ::: "memory");
    __syncthreads();
    D_ISSUE(0);

    for (int tau = 1; tau < 48; tau++) {
        int tm1 = tau - 1;
        // MMA(tau-1) must be done before overwriting the single A buffer
        mbar_wait_parity(sCtl + 8 + (tm1 & 1) * 8, (unsigned)((tm1 >> 1) & 1));
        asm volatile("tcgen05.fence::after_thread_sync;" ::: "memory");
        d_stage(tid, tau, lbase, n, w0, pA);
        asm volatile("fence.proxy.async.shared::cta;" ::: "memory");
        __syncthreads();
        D_ISSUE(tau);          // overlaps epilogue(tau-1) below
        d_epilogue(tid, tm1, lbase, n, w0, tmem, sbo, spa, out);
        __syncthreads();       // epilogue done before next iteration's ISSUE reuses TMEM
    }
    mbar_wait_parity(sCtl + 8 + (47 & 1) * 8, (unsigned)((47 >> 1) & 1));
    asm volatile("tcgen05.fence::after_thread_sync;" ::: "memory");
    d_epilogue(tid, 47, lbase, n, w0, tmem, sbo, spa, out);
    #undef D_ISSUE

    __syncthreads();
    if (wid == 0)
        asm volatile("tcgen05.dealloc.cta_group::1.sync.aligned.b32 %0, %1;"
                     :: "r"(tmem), "r"(128));
    if (tid == 0) {
        asm volatile("mbarrier.inval.shared.b64 [%0];" :: "r"(sCtl + 8) : "memory");
        asm volatile("mbarrier.inval.shared.b64 [%0];" :: "r"(sCtl + 16) : "memory");
    }
#else
    __syncthreads();
    int lend = (lbase + 48 < 94) ? (lbase + 48) : 94;
    int nl = lend - lbase;
    for (int i = tid; i < 64 * 128 * nl; i += 256) {
        int o = i / (128 * nl);
        int r = i % (128 * nl);
        int wi = r / nl, l = lbase + r % nl;
        int w = w0 + wi;
        if (w < V_) {
            float acc = bout[o];
            for (int k = 0; k < 96; k++) {
                int hop = k >> 5, c = k & 31;
                float h;
                if (hop == 0) h = g_xt[((size_t)(n * CIN + c) * LP + l) * VP + w];
                else h = g_x12[((size_t)(((hop - 1) * N_ + n) * CIN + c) * L_ + l) * VP + w];
                acc = fmaf(wout[o * 96 + k], h, acc);
            }
            acc = acc > 0.f ? acc : spa * acc;
            out[(((size_t)n * COUT + o) * V_ + w) * L_ + l] = acc;
        }
    }
#endif
}

// ---------------------------------------------------------------------------
extern "C" void kernel_launch(void* const* d_in, const int* in_sizes, int n_in,
                              void* d_out, int out_size) {
    const float* x    = (const float*)d_in[0];
    const float* A    = (const float*)d_in[1];
    const float* w1   = (const float*)d_in[2];
    const float* b1   = (const float*)d_in[3];
    const float* w2   = (const float*)d_in[4];
    const float* b2   = (const float*)d_in[5];
    const float* w3   = (const float*)d_in[6];
    const float* b3   = (const float*)d_in[7];
    const float* wout = (const float*)d_in[8];
    const float* bout = (const float*)d_in[9];
    const float* pa   = (const float*)d_in[10];
    float* out = (float*)d_out;

    cudaFuncSetAttribute(kernelC,     cudaFuncAttributeMaxDynamicSharedMemorySize, C_SMEM_BYTES);
    cudaFuncSetAttribute(kernelB_mma, cudaFuncAttributeMaxDynamicSharedMemorySize, BM_SMEM);
    cudaFuncSetAttribute(kernelD_mma, cudaFuncAttributeMaxDynamicSharedMemorySize, D_SMEM);
    cudaFuncSetAttribute(kernelX,     cudaFuncAttributeMaxDynamicSharedMemorySize, X_SMEM);

    kernelA<<<dim3(32, 32), dim3(16, 16)>>>(A);
    kernelW<<<48, 256>>>(w1, w2, w3);
    kernelX<<<dim3(125, 32), 256, X_SMEM>>>(x);
    kernelB_mma<<<dim3(4, 64), 256, BM_SMEM>>>(b1, b2, b3);
    kernelC<<<dim3(4, 24, 32), 256, C_SMEM_BYTES>>>();
    kernelD_mma<<<dim3(4, 64), 256, D_SMEM>>>(wout, bout, pa, out);
}